// round 12
// baseline (speedup 1.0000x reference)
#include <cuda_runtime.h>
#include <cuda_fp16.h>
#include <math.h>
#include <stdint.h>

// ---------------------------------------------------------------------------
// Problem constants: B=8, S=1024, D=1024, H=16, DK=64, MLP=4096, tokens=8192
// ---------------------------------------------------------------------------
#define TOK    8192
#define DMODEL 1024
#define NHEAD  16
#define DKH    64
#define DMLP   4096

// ---------------------------------------------------------------------------
// Scratch (device globals; no allocation allowed)
// ---------------------------------------------------------------------------
__device__ __half g_h   [TOK * DMODEL];
__device__ __half g_qkv [TOK * 3 * DMODEL];
__device__ __half g_ctx [TOK * DMODEL];
__device__ float  g_out1[TOK * DMODEL];
__device__ __half g_h2  [TOK * DMODEL];
__device__ __half g_ff  [TOK * DMLP];
__device__ __half g_wh  [12 * 1024 * 1024];  // wqkvT(3M) woT(1M) w1T(4M) w2T(4M)
__device__ float  g_bqkv[3072];

__device__ __forceinline__ uint32_t s2u(const void* p) {
    uint32_t a;
    asm("{ .reg .u64 t; cvta.to.shared.u64 t, %1; cvt.u32.u64 %0, t; }" : "=r"(a) : "l"(p));
    return a;
}
__device__ __forceinline__ void cpa16(uint32_t dst, const void* src) {
    asm volatile("cp.async.cg.shared.global [%0], [%1], 16;" :: "r"(dst), "l"(src) : "memory");
}
__device__ __forceinline__ uint32_t h2u(__half2 h) {
    union { __half2 h; uint32_t u; } c; c.h = h; return c.u;
}

// ---------------------------------------------------------------------------
// Weight prep: four 1024x1024 transposes in one launch (z selects matrix).
// z=0: wq->wqkvT row 0 (scale 1/8); z=1: wk->+1024; z=2: wv->+2048; z=3: wo->woT
// ---------------------------------------------------------------------------
__global__ __launch_bounds__(256) void transw4_kernel(
    const float* __restrict__ wq, const float* __restrict__ wk,
    const float* __restrict__ wv, const float* __restrict__ wo,
    __half* __restrict__ wqkvT, __half* __restrict__ woT)
{
    __shared__ float t[32][33];
    int z = blockIdx.z;
    const float* src = (z == 0) ? wq : (z == 1) ? wk : (z == 2) ? wv : wo;
    __half* dst = (z == 3) ? woT : (wqkvT + (size_t)z * 1024 * 1024);
    float scale = (z == 0) ? 0.125f : 1.f;
    int n0 = blockIdx.x * 32, k0 = blockIdx.y * 32;
    int tx = threadIdx.x & 31, ty = (threadIdx.x >> 5) * 4;
    #pragma unroll
    for (int i = 0; i < 4; i++)
        t[ty + i][tx] = src[(size_t)(k0 + ty + i) * 1024 + n0 + tx] * scale;
    __syncthreads();
    #pragma unroll
    for (int i = 0; i < 4; i++)
        dst[(size_t)(n0 + ty + i) * 1024 + k0 + tx] = __float2half_rn(t[tx][ty + i]);
}
// generic transpose for w1 / w2
__global__ __launch_bounds__(256) void transw_kernel(
    const float* __restrict__ src, __half* __restrict__ dst, int Kd, int Nd)
{
    __shared__ float t[32][33];
    int n0 = blockIdx.x * 32, k0 = blockIdx.y * 32;
    int tx = threadIdx.x & 31, ty = (threadIdx.x >> 5) * 4;
    #pragma unroll
    for (int i = 0; i < 4; i++)
        t[ty + i][tx] = src[(size_t)(k0 + ty + i) * Nd + n0 + tx];
    __syncthreads();
    #pragma unroll
    for (int i = 0; i < 4; i++)
        dst[(size_t)(n0 + ty + i) * Kd + k0 + tx] = __float2half_rn(t[tx][ty + i]);
}
__global__ __launch_bounds__(256) void packb_kernel(
    const float* __restrict__ bq, const float* __restrict__ bk,
    const float* __restrict__ bv, float* __restrict__ dst)
{
    int i = blockIdx.x * 256 + threadIdx.x;
    if (i < 3072)
        dst[i] = (i < 1024) ? bq[i] * 0.125f : (i < 2048) ? bk[i - 1024] : bv[i - 2048];
}

// ---------------------------------------------------------------------------
// LayerNorm: warp-per-row, shfl-only reduction, no block barriers.
// grid 1024, block 256 (8 rows/block). fp32 in, half out.
// ---------------------------------------------------------------------------
__global__ __launch_bounds__(256) void ln_kernel(
    const float* __restrict__ x, const float* __restrict__ w,
    const float* __restrict__ b, __half* __restrict__ out)
{
    int lane = threadIdx.x & 31;
    int row  = blockIdx.x * 8 + (threadIdx.x >> 5);
    const float4* xr = (const float4*)(x + (size_t)row * DMODEL);
    float4 v[8];
    float s = 0.f, sq = 0.f;
    #pragma unroll
    for (int i = 0; i < 8; i++) {
        v[i] = xr[lane + i * 32];
        s  += v[i].x + v[i].y + v[i].z + v[i].w;
        sq += v[i].x*v[i].x + v[i].y*v[i].y + v[i].z*v[i].z + v[i].w*v[i].w;
    }
    #pragma unroll
    for (int o = 16; o; o >>= 1) {
        s  += __shfl_xor_sync(0xffffffffu, s,  o);
        sq += __shfl_xor_sync(0xffffffffu, sq, o);
    }
    float mu = s * (1.0f / DMODEL);
    float r  = rsqrtf(sq * (1.0f / DMODEL) - mu * mu + 1e-5f);
    __half2* orow = (__half2*)(out + (size_t)row * DMODEL);
    #pragma unroll
    for (int i = 0; i < 8; i++) {
        int idx = lane + i * 32;
        float4 w4 = ((const float4*)w)[idx];
        float4 b4 = ((const float4*)b)[idx];
        orow[idx * 2 + 0] = __floats2half2_rn((v[i].x - mu) * r * w4.x + b4.x,
                                              (v[i].y - mu) * r * w4.y + b4.y);
        orow[idx * 2 + 1] = __floats2half2_rn((v[i].z - mu) * r * w4.z + b4.z,
                                              (v[i].w - mu) * r * w4.w + b4.w);
    }
}

// ---------------------------------------------------------------------------
// fp16 mma.sync GEMM: 3-stage cp.async ring, ONE barrier per stage.
// A[M][K] half, Bt[N][K] half, fp32 accum.
// modes: 0 half out; 1 fp32 relu(v)+res; 2 half gelu(v); 3 fp32 v+res
// CTA 128x128, 8 warps 2m x 4n (64x32), BK=64.
// ---------------------------------------------------------------------------
#define HP 72
#define HTILE (128 * HP)
#define HSTG  (2 * HTILE)
#define GEMM_SMEM_BYTES (3 * HSTG * 2)

__global__ __launch_bounds__(256, 2) void tgemm_kernel(
    const __half* __restrict__ A, const __half* __restrict__ Bt,
    const float* __restrict__ bias, const float* __restrict__ res,
    float* __restrict__ C, int M, int N, int K, int mode)
{
    extern __shared__ __half smh[];
    uint32_t smb = s2u(smh);

    int tid  = threadIdx.x;
    int lane = tid & 31;
    int wid  = tid >> 5;
    int wm   = wid >> 2;
    int wn   = wid & 3;
    int lr   = lane >> 2;
    int lc   = lane & 3;

    int bn = blockIdx.x * 128;
    int bm = blockIdx.y * 128;

    int mat = lane >> 3;
    uint32_t aoff = (uint32_t)(((wm * 64 + (lane & 7) + ((mat & 1) << 3)) * HP
                               + ((mat >> 1) << 3)) * 2);
    uint32_t boff = (uint32_t)(((wn * 32 + ((mat >> 1) << 3) + (lane & 7)) * HP
                               + ((mat & 1) << 3)) * 2);

    float acc[4][4][4];
    #pragma unroll
    for (int i = 0; i < 4; i++)
        #pragma unroll
        for (int j = 0; j < 4; j++)
            #pragma unroll
            for (int q = 0; q < 4; q++) acc[i][j][q] = 0.f;

    int NS = K >> 6;

    #pragma unroll
    for (int st = 0; st < 2; st++) {
        uint32_t Ab = smb + (uint32_t)st * HSTG * 2;
        uint32_t Bb = Ab + HTILE * 2;
        int k0 = st * 64;
        #pragma unroll
        for (int t = 0; t < 4; t++) {
            int idx = tid + t * 256;
            int r = idx >> 3, ch = idx & 7;
            cpa16(Ab + (uint32_t)(r * HP + ch * 8) * 2,
                  A + (size_t)(bm + r) * K + k0 + ch * 8);
            cpa16(Bb + (uint32_t)(r * HP + ch * 8) * 2,
                  Bt + (size_t)(bn + r) * K + k0 + ch * 8);
        }
        asm volatile("cp.async.commit_group;" ::: "memory");
    }

    for (int s = 0; s < NS; s++) {
        if (s + 1 < NS) asm volatile("cp.async.wait_group 1;" ::: "memory");
        else            asm volatile("cp.async.wait_group 0;" ::: "memory");
        __syncthreads();

        // refill ring slot (s+2)%3 — its readers finished at stage s-1,
        // which the barrier above already ordered.
        if (s + 2 < NS) {
            int b3 = (s + 2) % 3;
            uint32_t Ab2 = smb + (uint32_t)b3 * HSTG * 2;
            uint32_t Bb2 = Ab2 + HTILE * 2;
            int k0 = (s + 2) * 64;
            #pragma unroll
            for (int t = 0; t < 4; t++) {
                int idx = tid + t * 256;
                int r = idx >> 3, ch = idx & 7;
                cpa16(Ab2 + (uint32_t)(r * HP + ch * 8) * 2,
                      A + (size_t)(bm + r) * K + k0 + ch * 8);
                cpa16(Bb2 + (uint32_t)(r * HP + ch * 8) * 2,
                      Bt + (size_t)(bn + r) * K + k0 + ch * 8);
            }
            asm volatile("cp.async.commit_group;" ::: "memory");
        }

        int cb = s % 3;
        uint32_t Ab = smb + (uint32_t)cb * HSTG * 2;
        uint32_t Bb = Ab + HTILE * 2;

        #pragma unroll
        for (int kk = 0; kk < 4; kk++) {
            uint32_t af[4][4];
            #pragma unroll
            for (int mt = 0; mt < 4; mt++) {
                asm volatile(
                    "ldmatrix.sync.aligned.m8n8.x4.shared.b16 {%0,%1,%2,%3}, [%4];"
                    : "=r"(af[mt][0]), "=r"(af[mt][1]), "=r"(af[mt][2]), "=r"(af[mt][3])
                    : "r"(Ab + aoff + (uint32_t)((mt * 16 * HP + kk * 16) * 2)));
            }
            uint32_t bf[4][2];
            #pragma unroll
            for (int p = 0; p < 2; p++) {
                asm volatile(
                    "ldmatrix.sync.aligned.m8n8.x4.shared.b16 {%0,%1,%2,%3}, [%4];"
                    : "=r"(bf[2*p][0]), "=r"(bf[2*p][1]),
                      "=r"(bf[2*p+1][0]), "=r"(bf[2*p+1][1])
                    : "r"(Bb + boff + (uint32_t)((p * 16 * HP + kk * 16) * 2)));
            }
            #pragma unroll
            for (int mt = 0; mt < 4; mt++)
                #pragma unroll
                for (int nt = 0; nt < 4; nt++) {
                    asm volatile(
                        "mma.sync.aligned.m16n8k16.row.col.f32.f16.f16.f32 "
                        "{%0,%1,%2,%3}, {%4,%5,%6,%7}, {%8,%9}, {%0,%1,%2,%3};"
                        : "+f"(acc[mt][nt][0]), "+f"(acc[mt][nt][1]),
                          "+f"(acc[mt][nt][2]), "+f"(acc[mt][nt][3])
                        : "r"(af[mt][0]), "r"(af[mt][1]), "r"(af[mt][2]), "r"(af[mt][3]),
                          "r"(bf[nt][0]), "r"(bf[nt][1]));
                }
        }
    }

    // ---- epilogue ----
    #pragma unroll
    for (int mt = 0; mt < 4; mt++) {
        #pragma unroll
        for (int half_ = 0; half_ < 2; half_++) {
            int row = bm + wm * 64 + mt * 16 + lr + half_ * 8;
            const float* rr = (mode == 1 || mode == 3) ? (res + (size_t)row * N) : nullptr;
            #pragma unroll
            for (int nt = 0; nt < 4; nt++) {
                int col = bn + wn * 32 + nt * 8 + lc * 2;
                float v0 = acc[mt][nt][half_ * 2 + 0] + bias[col];
                float v1 = acc[mt][nt][half_ * 2 + 1] + bias[col + 1];
                if (mode == 0) {
                    *(__half2*)((__half*)C + (size_t)row * N + col) = __floats2half2_rn(v0, v1);
                } else if (mode == 1) {
                    float2 o; o.x = fmaxf(v0, 0.f) + rr[col]; o.y = fmaxf(v1, 0.f) + rr[col + 1];
                    *(float2*)(C + (size_t)row * N + col) = o;
                } else if (mode == 2) {
                    v0 = 0.5f * v0 * (1.f + erff(v0 * 0.70710678118654752f));
                    v1 = 0.5f * v1 * (1.f + erff(v1 * 0.70710678118654752f));
                    *(__half2*)((__half*)C + (size_t)row * N + col) = __floats2half2_rn(v0, v1);
                } else {
                    float2 o; o.x = v0 + rr[col]; o.y = v1 + rr[col + 1];
                    *(float2*)(C + (size_t)row * N + col) = o;
                }
            }
        }
    }
}

// ---------------------------------------------------------------------------
// Flash attention, fp16 mma, cp.async double-buffered K/V.
// grid (8, 128), 256 thr, warp = 16 q-rows. P in registers; V ldmatrix.trans.
// smem: sQ[128][72], sK[2][64][72], sV[2][64][72] halves = 55296 B.
// ---------------------------------------------------------------------------
#define SP 72
#define KVT (64 * SP)
#define SQ_OFF 0
#define SK_OFF (128 * SP)
#define SV_OFF (SK_OFF + 2 * KVT)
#define ATTN_SMEM_BYTES ((SV_OFF + 2 * KVT) * 2)

__global__ __launch_bounds__(256, 2) void attn_kernel(
    const __half* __restrict__ QKV, __half* __restrict__ Og)
{
    extern __shared__ __half smh[];
    __half* sQ = smh + SQ_OFF;

    int bh = blockIdx.y;
    int b  = bh >> 4;
    int h  = bh & 15;
    int q0 = blockIdx.x * 128;

    size_t base = (size_t)b * 1024 * 3072;
    const __half* Qb = QKV + base + h * DKH;
    const __half* Kb = QKV + base + 1024 + h * DKH;
    const __half* Vb = QKV + base + 2048 + h * DKH;
    __half* Ob = Og + (size_t)b * 1024 * DMODEL + h * DKH;

    int tid  = threadIdx.x;
    int lane = tid & 31;
    int wid  = tid >> 5;
    int lr   = lane >> 2;
    int lc   = lane & 3;
    int mat  = lane >> 3;

    uint32_t sQb = s2u(sQ);
    uint32_t sKb0 = s2u(smh + SK_OFF);
    uint32_t sVb0 = s2u(smh + SV_OFF);
    uint32_t aoffQ = (uint32_t)(((wid * 16 + (lane & 7) + ((mat & 1) << 3)) * SP
                                + ((mat >> 1) << 3)) * 2);
    uint32_t koff  = (uint32_t)(((((mat >> 1) << 3) + (lane & 7)) * SP
                                + ((mat & 1) << 3)) * 2);
    uint32_t voff  = (uint32_t)(((((mat & 1) << 3) + (lane & 7)) * SP
                                + ((mat >> 1) << 3)) * 2);

    // load Q tile (128 x 64 halves) direct
    #pragma unroll
    for (int it = 0; it < 4; it++) {
        int idx = tid + it * 256;
        int r = idx >> 3, ch = idx & 7;
        *(uint4*)(sQ + r * SP + ch * 8) =
            *(const uint4*)(Qb + (size_t)(q0 + r) * 3072 + ch * 8);
    }

    // prologue: stage kt=0 K/V via cp.async
    #pragma unroll
    for (int it = 0; it < 2; it++) {
        int idx = tid + it * 256;
        int r = idx >> 3, ch = idx & 7;
        cpa16(sKb0 + (uint32_t)(r * SP + ch * 8) * 2,
              Kb + (size_t)r * 3072 + ch * 8);
        cpa16(sVb0 + (uint32_t)(r * SP + ch * 8) * 2,
              Vb + (size_t)r * 3072 + ch * 8);
    }
    asm volatile("cp.async.commit_group;" ::: "memory");

    float m0 = -1e30f, m1 = -1e30f, l0 = 0.f, l1 = 0.f;
    float o[8][4];
    #pragma unroll
    for (int nt = 0; nt < 8; nt++)
        #pragma unroll
        for (int q = 0; q < 4; q++) o[nt][q] = 0.f;

    for (int kt = 0; kt < 16; kt++) {
        asm volatile("cp.async.wait_group 0;" ::: "memory");
        __syncthreads();

        if (kt + 1 < 16) {
            int nb = (kt + 1) & 1;
            uint32_t Kd = sKb0 + (uint32_t)(nb * KVT) * 2;
            uint32_t Vd = sVb0 + (uint32_t)(nb * KVT) * 2;
            #pragma unroll
            for (int it = 0; it < 2; it++) {
                int idx = tid + it * 256;
                int r = idx >> 3, ch = idx & 7;
                cpa16(Kd + (uint32_t)(r * SP + ch * 8) * 2,
                      Kb + (size_t)((kt + 1) * 64 + r) * 3072 + ch * 8);
                cpa16(Vd + (uint32_t)(r * SP + ch * 8) * 2,
                      Vb + (size_t)((kt + 1) * 64 + r) * 3072 + ch * 8);
            }
            asm volatile("cp.async.commit_group;" ::: "memory");
        }

        uint32_t sKb = sKb0 + (uint32_t)((kt & 1) * KVT) * 2;
        uint32_t sVb = sVb0 + (uint32_t)((kt & 1) * KVT) * 2;

        // S = Q K^T : 16 x 64 per warp
        float sc[8][4];
        #pragma unroll
        for (int nt = 0; nt < 8; nt++)
            #pragma unroll
            for (int q = 0; q < 4; q++) sc[nt][q] = 0.f;

        #pragma unroll
        for (int kk = 0; kk < 4; kk++) {
            uint32_t a0, a1, a2, a3;
            asm volatile(
                "ldmatrix.sync.aligned.m8n8.x4.shared.b16 {%0,%1,%2,%3}, [%4];"
                : "=r"(a0), "=r"(a1), "=r"(a2), "=r"(a3)
                : "r"(sQb + aoffQ + (uint32_t)(kk * 32)));
            uint32_t kf[8][2];
            #pragma unroll
            for (int p = 0; p < 4; p++) {
                asm volatile(
                    "ldmatrix.sync.aligned.m8n8.x4.shared.b16 {%0,%1,%2,%3}, [%4];"
                    : "=r"(kf[2*p][0]), "=r"(kf[2*p][1]),
                      "=r"(kf[2*p+1][0]), "=r"(kf[2*p+1][1])
                    : "r"(sKb + koff + (uint32_t)((p * 16 * SP + kk * 16) * 2)));
            }
            #pragma unroll
            for (int nt = 0; nt < 8; nt++) {
                asm volatile(
                    "mma.sync.aligned.m16n8k16.row.col.f32.f16.f16.f32 "
                    "{%0,%1,%2,%3}, {%4,%5,%6,%7}, {%8,%9}, {%0,%1,%2,%3};"
                    : "+f"(sc[nt][0]), "+f"(sc[nt][1]), "+f"(sc[nt][2]), "+f"(sc[nt][3])
                    : "r"(a0), "r"(a1), "r"(a2), "r"(a3),
                      "r"(kf[nt][0]), "r"(kf[nt][1]));
            }
        }

        // online softmax (rows lr and lr+8)
        float x0 = -1e30f, x1 = -1e30f;
        #pragma unroll
        for (int nt = 0; nt < 8; nt++) {
            x0 = fmaxf(x0, fmaxf(sc[nt][0], sc[nt][1]));
            x1 = fmaxf(x1, fmaxf(sc[nt][2], sc[nt][3]));
        }
        x0 = fmaxf(x0, __shfl_xor_sync(0xffffffffu, x0, 1));
        x0 = fmaxf(x0, __shfl_xor_sync(0xffffffffu, x0, 2));
        x1 = fmaxf(x1, __shfl_xor_sync(0xffffffffu, x1, 1));
        x1 = fmaxf(x1, __shfl_xor_sync(0xffffffffu, x1, 2));
        float mn0 = fmaxf(m0, x0), mn1 = fmaxf(m1, x1);
        float al0 = __expf(m0 - mn0), al1 = __expf(m1 - mn1);
        float su0 = 0.f, su1 = 0.f;
        #pragma unroll
        for (int nt = 0; nt < 8; nt++) {
            sc[nt][0] = __expf(sc[nt][0] - mn0);
            sc[nt][1] = __expf(sc[nt][1] - mn0);
            sc[nt][2] = __expf(sc[nt][2] - mn1);
            sc[nt][3] = __expf(sc[nt][3] - mn1);
            su0 += sc[nt][0] + sc[nt][1];
            su1 += sc[nt][2] + sc[nt][3];
            o[nt][0] *= al0; o[nt][1] *= al0;
            o[nt][2] *= al1; o[nt][3] *= al1;
        }
        su0 += __shfl_xor_sync(0xffffffffu, su0, 1);
        su0 += __shfl_xor_sync(0xffffffffu, su0, 2);
        su1 += __shfl_xor_sync(0xffffffffu, su1, 1);
        su1 += __shfl_xor_sync(0xffffffffu, su1, 2);
        l0 = l0 * al0 + su0;
        l1 = l1 * al1 + su1;
        m0 = mn0; m1 = mn1;

        // O += P @ V : P from registers, V via ldmatrix.trans
        #pragma unroll
        for (int kk = 0; kk < 4; kk++) {
            uint32_t pa0 = h2u(__floats2half2_rn(sc[2*kk][0],   sc[2*kk][1]));
            uint32_t pa1 = h2u(__floats2half2_rn(sc[2*kk][2],   sc[2*kk][3]));
            uint32_t pa2 = h2u(__floats2half2_rn(sc[2*kk+1][0], sc[2*kk+1][1]));
            uint32_t pa3 = h2u(__floats2half2_rn(sc[2*kk+1][2], sc[2*kk+1][3]));
            #pragma unroll
            for (int p = 0; p < 4; p++) {
                uint32_t vf[2][2];
                asm volatile(
                    "ldmatrix.sync.aligned.m8n8.x4.trans.shared.b16 {%0,%1,%2,%3}, [%4];"
                    : "=r"(vf[0][0]), "=r"(vf[0][1]), "=r"(vf[1][0]), "=r"(vf[1][1])
                    : "r"(sVb + voff + (uint32_t)((kk * 16 * SP + p * 16) * 2)));
                #pragma unroll
                for (int g = 0; g < 2; g++) {
                    int nt = p * 2 + g;
                    asm volatile(
                        "mma.sync.aligned.m16n8k16.row.col.f32.f16.f16.f32 "
                        "{%0,%1,%2,%3}, {%4,%5,%6,%7}, {%8,%9}, {%0,%1,%2,%3};"
                        : "+f"(o[nt][0]), "+f"(o[nt][1]), "+f"(o[nt][2]), "+f"(o[nt][3])
                        : "r"(pa0), "r"(pa1), "r"(pa2), "r"(pa3),
                          "r"(vf[g][0]), "r"(vf[g][1]));
                }
            }
        }
    }

    // epilogue: normalize, store half
    float inv0 = 1.f / l0, inv1 = 1.f / l1;
    int row0 = q0 + wid * 16 + lr;
    int row1 = row0 + 8;
    #pragma unroll
    for (int nt = 0; nt < 8; nt++) {
        int col = nt * 8 + lc * 2;
        *(__half2*)(Ob + (size_t)row0 * DMODEL + col) =
            __floats2half2_rn(o[nt][0] * inv0, o[nt][1] * inv0);
        *(__half2*)(Ob + (size_t)row1 * DMODEL + col) =
            __floats2half2_rn(o[nt][2] * inv1, o[nt][3] * inv1);
    }
}

// ---------------------------------------------------------------------------
// Host launcher
// ---------------------------------------------------------------------------
extern "C" void kernel_launch(void* const* d_in, const int* in_sizes, int n_in,
                              void* d_out, int out_size)
{
    const float* x     = (const float*)d_in[0];
    const float* ln1_w = (const float*)d_in[1];
    const float* ln1_b = (const float*)d_in[2];
    const float* wq    = (const float*)d_in[3];
    const float* bq    = (const float*)d_in[4];
    const float* wk    = (const float*)d_in[5];
    const float* bk    = (const float*)d_in[6];
    const float* wv    = (const float*)d_in[7];
    const float* bv    = (const float*)d_in[8];
    const float* wo    = (const float*)d_in[9];
    const float* bo    = (const float*)d_in[10];
    const float* ln2_w = (const float*)d_in[11];
    const float* ln2_b = (const float*)d_in[12];
    const float* w1    = (const float*)d_in[13];
    const float* b1    = (const float*)d_in[14];
    const float* w2    = (const float*)d_in[15];
    const float* b2    = (const float*)d_in[16];

    __half *p_h, *p_qkv, *p_ctx, *p_h2, *p_ff, *p_wh;
    float *p_out1, *p_bqkv;
    cudaGetSymbolAddress((void**)&p_h,    g_h);
    cudaGetSymbolAddress((void**)&p_qkv,  g_qkv);
    cudaGetSymbolAddress((void**)&p_ctx,  g_ctx);
    cudaGetSymbolAddress((void**)&p_out1, g_out1);
    cudaGetSymbolAddress((void**)&p_h2,   g_h2);
    cudaGetSymbolAddress((void**)&p_ff,   g_ff);
    cudaGetSymbolAddress((void**)&p_wh,   g_wh);
    cudaGetSymbolAddress((void**)&p_bqkv, g_bqkv);

    const int MB = 1024 * 1024;
    __half* wqkvT = p_wh;               // [3072][1024]
    __half* woT   = p_wh + 3 * MB;      // [1024][1024]
    __half* w1T   = p_wh + 4 * MB;      // [4096][1024]
    __half* w2T   = p_wh + 8 * MB;      // [1024][4096]

    cudaFuncSetAttribute(attn_kernel, cudaFuncAttributeMaxDynamicSharedMemorySize,
                         ATTN_SMEM_BYTES);
    cudaFuncSetAttribute(tgemm_kernel, cudaFuncAttributeMaxDynamicSharedMemorySize,
                         GEMM_SMEM_BYTES);

    // 0) weight prep
    transw4_kernel<<<dim3(32, 32, 4), 256>>>(wq, wk, wv, wo, wqkvT, woT);
    transw_kernel<<<dim3(128, 32), 256>>>(w1, w1T, 1024, 4096);
    transw_kernel<<<dim3(32, 128), 256>>>(w2, w2T, 4096, 1024);
    packb_kernel<<<12, 256>>>(bq, bk, bv, p_bqkv);

    // 1) ln1 -> half
    ln_kernel<<<1024, 256>>>(x, ln1_w, ln1_b, p_h);
    // 2) fused QKV projection (half out)
    tgemm_kernel<<<dim3(24, 64), 256, GEMM_SMEM_BYTES>>>(
        p_h, wqkvT, p_bqkv, nullptr, (float*)p_qkv, TOK, 3 * DMODEL, DMODEL, 0);
    // 3) attention (fp16 mma, half out)
    attn_kernel<<<dim3(8, 128), 256, ATTN_SMEM_BYTES>>>(p_qkv, p_ctx);
    // 4) out proj + relu + residual(x) -> fp32 out1
    tgemm_kernel<<<dim3(8, 64), 256, GEMM_SMEM_BYTES>>>(
        p_ctx, woT, bo, x, p_out1, TOK, DMODEL, DMODEL, 1);
    // 5) ln2 -> half
    ln_kernel<<<1024, 256>>>(p_out1, ln2_w, ln2_b, p_h2);
    // 6) MLP up + gelu (half out)
    tgemm_kernel<<<dim3(32, 64), 256, GEMM_SMEM_BYTES>>>(
        p_h2, w1T, b1, nullptr, (float*)p_ff, TOK, DMLP, DMODEL, 2);
    // 7) MLP down + residual(out1) -> fp32 d_out
    tgemm_kernel<<<dim3(8, 64), 256, GEMM_SMEM_BYTES>>>(
        p_ff, w2T, b2, p_out1, (float*)d_out, TOK, DMODEL, DMLP, 3);
}

// round 13
// speedup vs baseline: 1.5277x; 1.5277x over previous
#include <cuda_runtime.h>
#include <cuda_fp16.h>
#include <math.h>
#include <stdint.h>

// ---------------------------------------------------------------------------
// Problem constants: B=8, S=1024, D=1024, H=16, DK=64, MLP=4096, tokens=8192
// ---------------------------------------------------------------------------
#define TOK    8192
#define DMODEL 1024
#define NHEAD  16
#define DKH    64
#define DMLP   4096

// ---------------------------------------------------------------------------
// Scratch (device globals; no allocation allowed)
// ---------------------------------------------------------------------------
__device__ __half g_h   [TOK * DMODEL];
__device__ __half g_qkv [TOK * 3 * DMODEL];
__device__ __half g_ctx [TOK * DMODEL];
__device__ float  g_out1[TOK * DMODEL];
__device__ __half g_h2  [TOK * DMODEL];
__device__ __half g_ff  [TOK * DMLP];
__device__ __half g_wh  [12 * 1024 * 1024];  // wqkvT(3M) woT(1M) w1T(4M) w2T(4M)
__device__ float  g_bqkv[3072];

__device__ __forceinline__ uint32_t s2u(const void* p) {
    uint32_t a;
    asm("{ .reg .u64 t; cvta.to.shared.u64 t, %1; cvt.u32.u64 %0, t; }" : "=r"(a) : "l"(p));
    return a;
}
__device__ __forceinline__ void cpa16(uint32_t dst, const void* src) {
    asm volatile("cp.async.cg.shared.global [%0], [%1], 16;" :: "r"(dst), "l"(src) : "memory");
}
__device__ __forceinline__ uint32_t h2u(__half2 h) {
    union { __half2 h; uint32_t u; } c; c.h = h; return c.u;
}

// ---------------------------------------------------------------------------
// Weight prep: four 1024x1024 transposes in one launch (z selects matrix).
// ---------------------------------------------------------------------------
__global__ __launch_bounds__(256) void transw4_kernel(
    const float* __restrict__ wq, const float* __restrict__ wk,
    const float* __restrict__ wv, const float* __restrict__ wo,
    __half* __restrict__ wqkvT, __half* __restrict__ woT)
{
    __shared__ float t[32][33];
    int z = blockIdx.z;
    const float* src = (z == 0) ? wq : (z == 1) ? wk : (z == 2) ? wv : wo;
    __half* dst = (z == 3) ? woT : (wqkvT + (size_t)z * 1024 * 1024);
    float scale = (z == 0) ? 0.125f : 1.f;
    int n0 = blockIdx.x * 32, k0 = blockIdx.y * 32;
    int tx = threadIdx.x & 31, ty = (threadIdx.x >> 5) * 4;
    #pragma unroll
    for (int i = 0; i < 4; i++)
        t[ty + i][tx] = src[(size_t)(k0 + ty + i) * 1024 + n0 + tx] * scale;
    __syncthreads();
    #pragma unroll
    for (int i = 0; i < 4; i++)
        dst[(size_t)(n0 + ty + i) * 1024 + k0 + tx] = __float2half_rn(t[tx][ty + i]);
}
__global__ __launch_bounds__(256) void transw_kernel(
    const float* __restrict__ src, __half* __restrict__ dst, int Kd, int Nd)
{
    __shared__ float t[32][33];
    int n0 = blockIdx.x * 32, k0 = blockIdx.y * 32;
    int tx = threadIdx.x & 31, ty = (threadIdx.x >> 5) * 4;
    #pragma unroll
    for (int i = 0; i < 4; i++)
        t[ty + i][tx] = src[(size_t)(k0 + ty + i) * Nd + n0 + tx];
    __syncthreads();
    #pragma unroll
    for (int i = 0; i < 4; i++)
        dst[(size_t)(n0 + ty + i) * Kd + k0 + tx] = __float2half_rn(t[tx][ty + i]);
}
__global__ __launch_bounds__(256) void packb_kernel(
    const float* __restrict__ bq, const float* __restrict__ bk,
    const float* __restrict__ bv, float* __restrict__ dst)
{
    int i = blockIdx.x * 256 + threadIdx.x;
    if (i < 3072)
        dst[i] = (i < 1024) ? bq[i] * 0.125f : (i < 2048) ? bk[i - 1024] : bv[i - 2048];
}

// ---------------------------------------------------------------------------
// LayerNorm: warp-per-row, shfl-only reduction. grid 1024, block 256.
// ---------------------------------------------------------------------------
__global__ __launch_bounds__(256) void ln_kernel(
    const float* __restrict__ x, const float* __restrict__ w,
    const float* __restrict__ b, __half* __restrict__ out)
{
    int lane = threadIdx.x & 31;
    int row  = blockIdx.x * 8 + (threadIdx.x >> 5);
    const float4* xr = (const float4*)(x + (size_t)row * DMODEL);
    float4 v[8];
    float s = 0.f, sq = 0.f;
    #pragma unroll
    for (int i = 0; i < 8; i++) {
        v[i] = xr[lane + i * 32];
        s  += v[i].x + v[i].y + v[i].z + v[i].w;
        sq += v[i].x*v[i].x + v[i].y*v[i].y + v[i].z*v[i].z + v[i].w*v[i].w;
    }
    #pragma unroll
    for (int o = 16; o; o >>= 1) {
        s  += __shfl_xor_sync(0xffffffffu, s,  o);
        sq += __shfl_xor_sync(0xffffffffu, sq, o);
    }
    float mu = s * (1.0f / DMODEL);
    float r  = rsqrtf(sq * (1.0f / DMODEL) - mu * mu + 1e-5f);
    __half2* orow = (__half2*)(out + (size_t)row * DMODEL);
    #pragma unroll
    for (int i = 0; i < 8; i++) {
        int idx = lane + i * 32;
        float4 w4 = ((const float4*)w)[idx];
        float4 b4 = ((const float4*)b)[idx];
        orow[idx * 2 + 0] = __floats2half2_rn((v[i].x - mu) * r * w4.x + b4.x,
                                              (v[i].y - mu) * r * w4.y + b4.y);
        orow[idx * 2 + 1] = __floats2half2_rn((v[i].z - mu) * r * w4.z + b4.z,
                                              (v[i].w - mu) * r * w4.w + b4.w);
    }
}

// ---------------------------------------------------------------------------
// fp16 mma.sync GEMM — PROVEN R8 version: 2-stage cp.async, two barriers.
// A[M][K] half, Bt[N][K] half, fp32 accum.
// modes: 0 half out; 1 fp32 relu(v)+res; 2 half gelu(v); 3 fp32 v+res
// CTA 128x128, 8 warps 2m x 4n (64x32), BK=64. smem 73.7 KB -> 2 CTAs/SM.
// ---------------------------------------------------------------------------
#define HP 72
#define HTILE (128 * HP)
#define HSTG  (2 * HTILE)
#define GEMM_SMEM_BYTES (2 * HSTG * 2)

__global__ __launch_bounds__(256, 2) void tgemm_kernel(
    const __half* __restrict__ A, const __half* __restrict__ Bt,
    const float* __restrict__ bias, const float* __restrict__ res,
    float* __restrict__ C, int M, int N, int K, int mode)
{
    extern __shared__ __half smh[];
    uint32_t smb = s2u(smh);

    int tid  = threadIdx.x;
    int lane = tid & 31;
    int wid  = tid >> 5;
    int wm   = wid >> 2;
    int wn   = wid & 3;
    int lr   = lane >> 2;
    int lc   = lane & 3;

    int bn = blockIdx.x * 128;
    int bm = blockIdx.y * 128;

    int mat = lane >> 3;
    uint32_t aoff = (uint32_t)(((wm * 64 + (lane & 7) + ((mat & 1) << 3)) * HP
                               + ((mat >> 1) << 3)) * 2);
    uint32_t boff = (uint32_t)(((wn * 32 + ((mat >> 1) << 3) + (lane & 7)) * HP
                               + ((mat & 1) << 3)) * 2);

    float acc[4][4][4];
    #pragma unroll
    for (int i = 0; i < 4; i++)
        #pragma unroll
        for (int j = 0; j < 4; j++)
            #pragma unroll
            for (int q = 0; q < 4; q++) acc[i][j][q] = 0.f;

    int NS = K >> 6;

    #pragma unroll
    for (int st = 0; st < 2; st++) {
        uint32_t Ab = smb + (uint32_t)st * HSTG * 2;
        uint32_t Bb = Ab + HTILE * 2;
        int k0 = st * 64;
        #pragma unroll
        for (int t = 0; t < 4; t++) {
            int idx = tid + t * 256;
            int r = idx >> 3, ch = idx & 7;
            cpa16(Ab + (uint32_t)(r * HP + ch * 8) * 2,
                  A + (size_t)(bm + r) * K + k0 + ch * 8);
            cpa16(Bb + (uint32_t)(r * HP + ch * 8) * 2,
                  Bt + (size_t)(bn + r) * K + k0 + ch * 8);
        }
        asm volatile("cp.async.commit_group;" ::: "memory");
    }

    for (int s = 0; s < NS; s++) {
        if (s + 1 < NS) asm volatile("cp.async.wait_group 1;" ::: "memory");
        else            asm volatile("cp.async.wait_group 0;" ::: "memory");
        __syncthreads();

        uint32_t Ab = smb + (uint32_t)(s & 1) * HSTG * 2;
        uint32_t Bb = Ab + HTILE * 2;

        #pragma unroll
        for (int kk = 0; kk < 4; kk++) {
            uint32_t af[4][4];
            #pragma unroll
            for (int mt = 0; mt < 4; mt++) {
                asm volatile(
                    "ldmatrix.sync.aligned.m8n8.x4.shared.b16 {%0,%1,%2,%3}, [%4];"
                    : "=r"(af[mt][0]), "=r"(af[mt][1]), "=r"(af[mt][2]), "=r"(af[mt][3])
                    : "r"(Ab + aoff + (uint32_t)((mt * 16 * HP + kk * 16) * 2)));
            }
            uint32_t bf[4][2];
            #pragma unroll
            for (int p = 0; p < 2; p++) {
                asm volatile(
                    "ldmatrix.sync.aligned.m8n8.x4.shared.b16 {%0,%1,%2,%3}, [%4];"
                    : "=r"(bf[2*p][0]), "=r"(bf[2*p][1]),
                      "=r"(bf[2*p+1][0]), "=r"(bf[2*p+1][1])
                    : "r"(Bb + boff + (uint32_t)((p * 16 * HP + kk * 16) * 2)));
            }
            #pragma unroll
            for (int mt = 0; mt < 4; mt++)
                #pragma unroll
                for (int nt = 0; nt < 4; nt++) {
                    asm volatile(
                        "mma.sync.aligned.m16n8k16.row.col.f32.f16.f16.f32 "
                        "{%0,%1,%2,%3}, {%4,%5,%6,%7}, {%8,%9}, {%0,%1,%2,%3};"
                        : "+f"(acc[mt][nt][0]), "+f"(acc[mt][nt][1]),
                          "+f"(acc[mt][nt][2]), "+f"(acc[mt][nt][3])
                        : "r"(af[mt][0]), "r"(af[mt][1]), "r"(af[mt][2]), "r"(af[mt][3]),
                          "r"(bf[nt][0]), "r"(bf[nt][1]));
                }
        }

        __syncthreads();
        if (s + 2 < NS) {
            uint32_t Ab2 = smb + (uint32_t)(s & 1) * HSTG * 2;
            uint32_t Bb2 = Ab2 + HTILE * 2;
            int k0 = (s + 2) * 64;
            #pragma unroll
            for (int t = 0; t < 4; t++) {
                int idx = tid + t * 256;
                int r = idx >> 3, ch = idx & 7;
                cpa16(Ab2 + (uint32_t)(r * HP + ch * 8) * 2,
                      A + (size_t)(bm + r) * K + k0 + ch * 8);
                cpa16(Bb2 + (uint32_t)(r * HP + ch * 8) * 2,
                      Bt + (size_t)(bn + r) * K + k0 + ch * 8);
            }
            asm volatile("cp.async.commit_group;" ::: "memory");
        }
    }

    // ---- epilogue ----
    #pragma unroll
    for (int mt = 0; mt < 4; mt++) {
        #pragma unroll
        for (int half_ = 0; half_ < 2; half_++) {
            int row = bm + wm * 64 + mt * 16 + lr + half_ * 8;
            const float* rr = (mode == 1 || mode == 3) ? (res + (size_t)row * N) : nullptr;
            #pragma unroll
            for (int nt = 0; nt < 4; nt++) {
                int col = bn + wn * 32 + nt * 8 + lc * 2;
                float v0 = acc[mt][nt][half_ * 2 + 0] + bias[col];
                float v1 = acc[mt][nt][half_ * 2 + 1] + bias[col + 1];
                if (mode == 0) {
                    *(__half2*)((__half*)C + (size_t)row * N + col) = __floats2half2_rn(v0, v1);
                } else if (mode == 1) {
                    float2 o; o.x = fmaxf(v0, 0.f) + rr[col]; o.y = fmaxf(v1, 0.f) + rr[col + 1];
                    *(float2*)(C + (size_t)row * N + col) = o;
                } else if (mode == 2) {
                    v0 = 0.5f * v0 * (1.f + erff(v0 * 0.70710678118654752f));
                    v1 = 0.5f * v1 * (1.f + erff(v1 * 0.70710678118654752f));
                    *(__half2*)((__half*)C + (size_t)row * N + col) = __floats2half2_rn(v0, v1);
                } else {
                    float2 o; o.x = v0 + rr[col]; o.y = v1 + rr[col + 1];
                    *(float2*)(C + (size_t)row * N + col) = o;
                }
            }
        }
    }
}

// ---------------------------------------------------------------------------
// Flash attention, fp16 mma, cp.async double-buffered K/V.
// grid (8, 128), 256 thr, warp = 16 q-rows. P in registers; V ldmatrix.trans.
// smem: sQ[128][72], sK[2][64][72], sV[2][64][72] halves = 55296 B.
// ---------------------------------------------------------------------------
#define SP 72
#define KVT (64 * SP)
#define SQ_OFF 0
#define SK_OFF (128 * SP)
#define SV_OFF (SK_OFF + 2 * KVT)
#define ATTN_SMEM_BYTES ((SV_OFF + 2 * KVT) * 2)

__global__ __launch_bounds__(256, 2) void attn_kernel(
    const __half* __restrict__ QKV, __half* __restrict__ Og)
{
    extern __shared__ __half smh[];
    __half* sQ = smh + SQ_OFF;

    int bh = blockIdx.y;
    int b  = bh >> 4;
    int h  = bh & 15;
    int q0 = blockIdx.x * 128;

    size_t base = (size_t)b * 1024 * 3072;
    const __half* Qb = QKV + base + h * DKH;
    const __half* Kb = QKV + base + 1024 + h * DKH;
    const __half* Vb = QKV + base + 2048 + h * DKH;
    __half* Ob = Og + (size_t)b * 1024 * DMODEL + h * DKH;

    int tid  = threadIdx.x;
    int lane = tid & 31;
    int wid  = tid >> 5;
    int lr   = lane >> 2;
    int lc   = lane & 3;
    int mat  = lane >> 3;

    uint32_t sQb = s2u(sQ);
    uint32_t sKb0 = s2u(smh + SK_OFF);
    uint32_t sVb0 = s2u(smh + SV_OFF);
    uint32_t aoffQ = (uint32_t)(((wid * 16 + (lane & 7) + ((mat & 1) << 3)) * SP
                                + ((mat >> 1) << 3)) * 2);
    uint32_t koff  = (uint32_t)(((((mat >> 1) << 3) + (lane & 7)) * SP
                                + ((mat & 1) << 3)) * 2);
    uint32_t voff  = (uint32_t)(((((mat & 1) << 3) + (lane & 7)) * SP
                                + ((mat >> 1) << 3)) * 2);

    // load Q tile (128 x 64 halves) direct
    #pragma unroll
    for (int it = 0; it < 4; it++) {
        int idx = tid + it * 256;
        int r = idx >> 3, ch = idx & 7;
        *(uint4*)(sQ + r * SP + ch * 8) =
            *(const uint4*)(Qb + (size_t)(q0 + r) * 3072 + ch * 8);
    }

    // prologue: stage kt=0 K/V via cp.async
    #pragma unroll
    for (int it = 0; it < 2; it++) {
        int idx = tid + it * 256;
        int r = idx >> 3, ch = idx & 7;
        cpa16(sKb0 + (uint32_t)(r * SP + ch * 8) * 2,
              Kb + (size_t)r * 3072 + ch * 8);
        cpa16(sVb0 + (uint32_t)(r * SP + ch * 8) * 2,
              Vb + (size_t)r * 3072 + ch * 8);
    }
    asm volatile("cp.async.commit_group;" ::: "memory");

    float m0 = -1e30f, m1 = -1e30f, l0 = 0.f, l1 = 0.f;
    float o[8][4];
    #pragma unroll
    for (int nt = 0; nt < 8; nt++)
        #pragma unroll
        for (int q = 0; q < 4; q++) o[nt][q] = 0.f;

    for (int kt = 0; kt < 16; kt++) {
        asm volatile("cp.async.wait_group 0;" ::: "memory");
        __syncthreads();

        if (kt + 1 < 16) {
            int nb = (kt + 1) & 1;
            uint32_t Kd = sKb0 + (uint32_t)(nb * KVT) * 2;
            uint32_t Vd = sVb0 + (uint32_t)(nb * KVT) * 2;
            #pragma unroll
            for (int it = 0; it < 2; it++) {
                int idx = tid + it * 256;
                int r = idx >> 3, ch = idx & 7;
                cpa16(Kd + (uint32_t)(r * SP + ch * 8) * 2,
                      Kb + (size_t)((kt + 1) * 64 + r) * 3072 + ch * 8);
                cpa16(Vd + (uint32_t)(r * SP + ch * 8) * 2,
                      Vb + (size_t)((kt + 1) * 64 + r) * 3072 + ch * 8);
            }
            asm volatile("cp.async.commit_group;" ::: "memory");
        }

        uint32_t sKb = sKb0 + (uint32_t)((kt & 1) * KVT) * 2;
        uint32_t sVb = sVb0 + (uint32_t)((kt & 1) * KVT) * 2;

        // S = Q K^T : 16 x 64 per warp
        float sc[8][4];
        #pragma unroll
        for (int nt = 0; nt < 8; nt++)
            #pragma unroll
            for (int q = 0; q < 4; q++) sc[nt][q] = 0.f;

        #pragma unroll
        for (int kk = 0; kk < 4; kk++) {
            uint32_t a0, a1, a2, a3;
            asm volatile(
                "ldmatrix.sync.aligned.m8n8.x4.shared.b16 {%0,%1,%2,%3}, [%4];"
                : "=r"(a0), "=r"(a1), "=r"(a2), "=r"(a3)
                : "r"(sQb + aoffQ + (uint32_t)(kk * 32)));
            uint32_t kf[8][2];
            #pragma unroll
            for (int p = 0; p < 4; p++) {
                asm volatile(
                    "ldmatrix.sync.aligned.m8n8.x4.shared.b16 {%0,%1,%2,%3}, [%4];"
                    : "=r"(kf[2*p][0]), "=r"(kf[2*p][1]),
                      "=r"(kf[2*p+1][0]), "=r"(kf[2*p+1][1])
                    : "r"(sKb + koff + (uint32_t)((p * 16 * SP + kk * 16) * 2)));
            }
            #pragma unroll
            for (int nt = 0; nt < 8; nt++) {
                asm volatile(
                    "mma.sync.aligned.m16n8k16.row.col.f32.f16.f16.f32 "
                    "{%0,%1,%2,%3}, {%4,%5,%6,%7}, {%8,%9}, {%0,%1,%2,%3};"
                    : "+f"(sc[nt][0]), "+f"(sc[nt][1]), "+f"(sc[nt][2]), "+f"(sc[nt][3])
                    : "r"(a0), "r"(a1), "r"(a2), "r"(a3),
                      "r"(kf[nt][0]), "r"(kf[nt][1]));
            }
        }

        // online softmax (rows lr and lr+8)
        float x0 = -1e30f, x1 = -1e30f;
        #pragma unroll
        for (int nt = 0; nt < 8; nt++) {
            x0 = fmaxf(x0, fmaxf(sc[nt][0], sc[nt][1]));
            x1 = fmaxf(x1, fmaxf(sc[nt][2], sc[nt][3]));
        }
        x0 = fmaxf(x0, __shfl_xor_sync(0xffffffffu, x0, 1));
        x0 = fmaxf(x0, __shfl_xor_sync(0xffffffffu, x0, 2));
        x1 = fmaxf(x1, __shfl_xor_sync(0xffffffffu, x1, 1));
        x1 = fmaxf(x1, __shfl_xor_sync(0xffffffffu, x1, 2));
        float mn0 = fmaxf(m0, x0), mn1 = fmaxf(m1, x1);
        float al0 = __expf(m0 - mn0), al1 = __expf(m1 - mn1);
        float su0 = 0.f, su1 = 0.f;
        #pragma unroll
        for (int nt = 0; nt < 8; nt++) {
            sc[nt][0] = __expf(sc[nt][0] - mn0);
            sc[nt][1] = __expf(sc[nt][1] - mn0);
            sc[nt][2] = __expf(sc[nt][2] - mn1);
            sc[nt][3] = __expf(sc[nt][3] - mn1);
            su0 += sc[nt][0] + sc[nt][1];
            su1 += sc[nt][2] + sc[nt][3];
            o[nt][0] *= al0; o[nt][1] *= al0;
            o[nt][2] *= al1; o[nt][3] *= al1;
        }
        su0 += __shfl_xor_sync(0xffffffffu, su0, 1);
        su0 += __shfl_xor_sync(0xffffffffu, su0, 2);
        su1 += __shfl_xor_sync(0xffffffffu, su1, 1);
        su1 += __shfl_xor_sync(0xffffffffu, su1, 2);
        l0 = l0 * al0 + su0;
        l1 = l1 * al1 + su1;
        m0 = mn0; m1 = mn1;

        // O += P @ V : P from registers, V via ldmatrix.trans
        #pragma unroll
        for (int kk = 0; kk < 4; kk++) {
            uint32_t pa0 = h2u(__floats2half2_rn(sc[2*kk][0],   sc[2*kk][1]));
            uint32_t pa1 = h2u(__floats2half2_rn(sc[2*kk][2],   sc[2*kk][3]));
            uint32_t pa2 = h2u(__floats2half2_rn(sc[2*kk+1][0], sc[2*kk+1][1]));
            uint32_t pa3 = h2u(__floats2half2_rn(sc[2*kk+1][2], sc[2*kk+1][3]));
            #pragma unroll
            for (int p = 0; p < 4; p++) {
                uint32_t vf[2][2];
                asm volatile(
                    "ldmatrix.sync.aligned.m8n8.x4.trans.shared.b16 {%0,%1,%2,%3}, [%4];"
                    : "=r"(vf[0][0]), "=r"(vf[0][1]), "=r"(vf[1][0]), "=r"(vf[1][1])
                    : "r"(sVb + voff + (uint32_t)((kk * 16 * SP + p * 16) * 2)));
                #pragma unroll
                for (int g = 0; g < 2; g++) {
                    int nt = p * 2 + g;
                    asm volatile(
                        "mma.sync.aligned.m16n8k16.row.col.f32.f16.f16.f32 "
                        "{%0,%1,%2,%3}, {%4,%5,%6,%7}, {%8,%9}, {%0,%1,%2,%3};"
                        : "+f"(o[nt][0]), "+f"(o[nt][1]), "+f"(o[nt][2]), "+f"(o[nt][3])
                        : "r"(pa0), "r"(pa1), "r"(pa2), "r"(pa3),
                          "r"(vf[g][0]), "r"(vf[g][1]));
                }
            }
        }
    }

    // epilogue: normalize, store half
    float inv0 = 1.f / l0, inv1 = 1.f / l1;
    int row0 = q0 + wid * 16 + lr;
    int row1 = row0 + 8;
    #pragma unroll
    for (int nt = 0; nt < 8; nt++) {
        int col = nt * 8 + lc * 2;
        *(__half2*)(Ob + (size_t)row0 * DMODEL + col) =
            __floats2half2_rn(o[nt][0] * inv0, o[nt][1] * inv0);
        *(__half2*)(Ob + (size_t)row1 * DMODEL + col) =
            __floats2half2_rn(o[nt][2] * inv1, o[nt][3] * inv1);
    }
}

// ---------------------------------------------------------------------------
// Host launcher
// ---------------------------------------------------------------------------
extern "C" void kernel_launch(void* const* d_in, const int* in_sizes, int n_in,
                              void* d_out, int out_size)
{
    const float* x     = (const float*)d_in[0];
    const float* ln1_w = (const float*)d_in[1];
    const float* ln1_b = (const float*)d_in[2];
    const float* wq    = (const float*)d_in[3];
    const float* bq    = (const float*)d_in[4];
    const float* wk    = (const float*)d_in[5];
    const float* bk    = (const float*)d_in[6];
    const float* wv    = (const float*)d_in[7];
    const float* bv    = (const float*)d_in[8];
    const float* wo    = (const float*)d_in[9];
    const float* bo    = (const float*)d_in[10];
    const float* ln2_w = (const float*)d_in[11];
    const float* ln2_b = (const float*)d_in[12];
    const float* w1    = (const float*)d_in[13];
    const float* b1    = (const float*)d_in[14];
    const float* w2    = (const float*)d_in[15];
    const float* b2    = (const float*)d_in[16];

    __half *p_h, *p_qkv, *p_ctx, *p_h2, *p_ff, *p_wh;
    float *p_out1, *p_bqkv;
    cudaGetSymbolAddress((void**)&p_h,    g_h);
    cudaGetSymbolAddress((void**)&p_qkv,  g_qkv);
    cudaGetSymbolAddress((void**)&p_ctx,  g_ctx);
    cudaGetSymbolAddress((void**)&p_out1, g_out1);
    cudaGetSymbolAddress((void**)&p_h2,   g_h2);
    cudaGetSymbolAddress((void**)&p_ff,   g_ff);
    cudaGetSymbolAddress((void**)&p_wh,   g_wh);
    cudaGetSymbolAddress((void**)&p_bqkv, g_bqkv);

    const int MB = 1024 * 1024;
    __half* wqkvT = p_wh;               // [3072][1024]
    __half* woT   = p_wh + 3 * MB;      // [1024][1024]
    __half* w1T   = p_wh + 4 * MB;      // [4096][1024]
    __half* w2T   = p_wh + 8 * MB;      // [1024][4096]

    cudaFuncSetAttribute(attn_kernel, cudaFuncAttributeMaxDynamicSharedMemorySize,
                         ATTN_SMEM_BYTES);
    cudaFuncSetAttribute(tgemm_kernel, cudaFuncAttributeMaxDynamicSharedMemorySize,
                         GEMM_SMEM_BYTES);

    // 0) weight prep
    transw4_kernel<<<dim3(32, 32, 4), 256>>>(wq, wk, wv, wo, wqkvT, woT);
    transw_kernel<<<dim3(128, 32), 256>>>(w1, w1T, 1024, 4096);
    transw_kernel<<<dim3(32, 128), 256>>>(w2, w2T, 4096, 1024);
    packb_kernel<<<12, 256>>>(bq, bk, bv, p_bqkv);

    // 1) ln1 -> half
    ln_kernel<<<1024, 256>>>(x, ln1_w, ln1_b, p_h);
    // 2) fused QKV projection (half out)
    tgemm_kernel<<<dim3(24, 64), 256, GEMM_SMEM_BYTES>>>(
        p_h, wqkvT, p_bqkv, nullptr, (float*)p_qkv, TOK, 3 * DMODEL, DMODEL, 0);
    // 3) attention (fp16 mma, half out)
    attn_kernel<<<dim3(8, 128), 256, ATTN_SMEM_BYTES>>>(p_qkv, p_ctx);
    // 4) out proj + relu + residual(x) -> fp32 out1
    tgemm_kernel<<<dim3(8, 64), 256, GEMM_SMEM_BYTES>>>(
        p_ctx, woT, bo, x, p_out1, TOK, DMODEL, DMODEL, 1);
    // 5) ln2 -> half
    ln_kernel<<<1024, 256>>>(p_out1, ln2_w, ln2_b, p_h2);
    // 6) MLP up + gelu (half out)
    tgemm_kernel<<<dim3(32, 64), 256, GEMM_SMEM_BYTES>>>(
        p_h2, w1T, b1, nullptr, (float*)p_ff, TOK, DMLP, DMODEL, 2);
    // 7) MLP down + residual(out1) -> fp32 d_out
    tgemm_kernel<<<dim3(8, 64), 256, GEMM_SMEM_BYTES>>>(
        p_ff, w2T, b2, p_out1, (float*)d_out, TOK, DMODEL, DMLP, 3);
}

// round 14
// speedup vs baseline: 1.7208x; 1.1264x over previous
#include <cuda_runtime.h>
#include <cuda_fp16.h>
#include <math.h>
#include <stdint.h>

// ---------------------------------------------------------------------------
// Problem constants: B=8, S=1024, D=1024, H=16, DK=64, MLP=4096, tokens=8192
// ---------------------------------------------------------------------------
#define TOK    8192
#define DMODEL 1024
#define NHEAD  16
#define DKH    64
#define DMLP   4096

// ---------------------------------------------------------------------------
// Scratch (device globals; no allocation allowed)
// ---------------------------------------------------------------------------
__device__ __half g_h   [TOK * DMODEL];
__device__ __half g_qkv [TOK * 3 * DMODEL];
__device__ __half g_ctx [TOK * DMODEL];
__device__ float  g_out1[TOK * DMODEL];
__device__ __half g_h2  [TOK * DMODEL];
__device__ __half g_ff  [TOK * DMLP];
__device__ __half g_wh  [12 * 1024 * 1024];  // wqkvT(3M) woT(1M) w1T(4M) w2T(4M)
__device__ float  g_bqkv[3072];

__device__ __forceinline__ uint32_t s2u(const void* p) {
    uint32_t a;
    asm("{ .reg .u64 t; cvta.to.shared.u64 t, %1; cvt.u32.u64 %0, t; }" : "=r"(a) : "l"(p));
    return a;
}
__device__ __forceinline__ void cpa16(uint32_t dst, const void* src) {
    asm volatile("cp.async.cg.shared.global [%0], [%1], 16;" :: "r"(dst), "l"(src) : "memory");
}
__device__ __forceinline__ uint32_t h2u(__half2 h) {
    union { __half2 h; uint32_t u; } c; c.h = h; return c.u;
}

// ---------------------------------------------------------------------------
// Weight prep: four 1024x1024 transposes in one launch (z selects matrix).
// z==0 blocks with blockIdx.y==0 additionally pack the QKV bias.
// ---------------------------------------------------------------------------
__global__ __launch_bounds__(256) void transw4_kernel(
    const float* __restrict__ wq, const float* __restrict__ wk,
    const float* __restrict__ wv, const float* __restrict__ wo,
    const float* __restrict__ bq, const float* __restrict__ bk,
    const float* __restrict__ bv, float* __restrict__ bqkv,
    __half* __restrict__ wqkvT, __half* __restrict__ woT)
{
    __shared__ float t[32][33];
    int z = blockIdx.z;
    const float* src = (z == 0) ? wq : (z == 1) ? wk : (z == 2) ? wv : wo;
    __half* dst = (z == 3) ? woT : (wqkvT + (size_t)z * 1024 * 1024);
    float scale = (z == 0) ? 0.125f : 1.f;
    int n0 = blockIdx.x * 32, k0 = blockIdx.y * 32;
    int tx = threadIdx.x & 31, ty = (threadIdx.x >> 5) * 4;
    #pragma unroll
    for (int i = 0; i < 4; i++)
        t[ty + i][tx] = src[(size_t)(k0 + ty + i) * 1024 + n0 + tx] * scale;
    __syncthreads();
    #pragma unroll
    for (int i = 0; i < 4; i++)
        dst[(size_t)(n0 + ty + i) * 1024 + k0 + tx] = __float2half_rn(t[tx][ty + i]);
    if (z == 0 && blockIdx.y == 0) {
        int i = blockIdx.x * 256 + threadIdx.x;
        if (i < 3072)
            bqkv[i] = (i < 1024) ? bq[i] * 0.125f
                    : (i < 2048) ? bk[i - 1024] : bv[i - 2048];
    }
}
__global__ __launch_bounds__(256) void transw_kernel(
    const float* __restrict__ src, __half* __restrict__ dst, int Kd, int Nd)
{
    __shared__ float t[32][33];
    int n0 = blockIdx.x * 32, k0 = blockIdx.y * 32;
    int tx = threadIdx.x & 31, ty = (threadIdx.x >> 5) * 4;
    #pragma unroll
    for (int i = 0; i < 4; i++)
        t[ty + i][tx] = src[(size_t)(k0 + ty + i) * Nd + n0 + tx];
    __syncthreads();
    #pragma unroll
    for (int i = 0; i < 4; i++)
        dst[(size_t)(n0 + ty + i) * Kd + k0 + tx] = __float2half_rn(t[tx][ty + i]);
}

// ---------------------------------------------------------------------------
// LayerNorm: warp-per-row, shfl-only reduction. grid 1024, block 256.
// ---------------------------------------------------------------------------
__global__ __launch_bounds__(256) void ln_kernel(
    const float* __restrict__ x, const float* __restrict__ w,
    const float* __restrict__ b, __half* __restrict__ out)
{
    int lane = threadIdx.x & 31;
    int row  = blockIdx.x * 8 + (threadIdx.x >> 5);
    const float4* xr = (const float4*)(x + (size_t)row * DMODEL);
    float4 v[8];
    float s = 0.f, sq = 0.f;
    #pragma unroll
    for (int i = 0; i < 8; i++) {
        v[i] = xr[lane + i * 32];
        s  += v[i].x + v[i].y + v[i].z + v[i].w;
        sq += v[i].x*v[i].x + v[i].y*v[i].y + v[i].z*v[i].z + v[i].w*v[i].w;
    }
    #pragma unroll
    for (int o = 16; o; o >>= 1) {
        s  += __shfl_xor_sync(0xffffffffu, s,  o);
        sq += __shfl_xor_sync(0xffffffffu, sq, o);
    }
    float mu = s * (1.0f / DMODEL);
    float r  = rsqrtf(sq * (1.0f / DMODEL) - mu * mu + 1e-5f);
    __half2* orow = (__half2*)(out + (size_t)row * DMODEL);
    #pragma unroll
    for (int i = 0; i < 8; i++) {
        int idx = lane + i * 32;
        float4 w4 = ((const float4*)w)[idx];
        float4 b4 = ((const float4*)b)[idx];
        orow[idx * 2 + 0] = __floats2half2_rn((v[i].x - mu) * r * w4.x + b4.x,
                                              (v[i].y - mu) * r * w4.y + b4.y);
        orow[idx * 2 + 1] = __floats2half2_rn((v[i].z - mu) * r * w4.z + b4.z,
                                              (v[i].w - mu) * r * w4.w + b4.w);
    }
}

// ---------------------------------------------------------------------------
// fp16 mma.sync GEMM v5: XOR-swizzled smem (pitch 64 halves / 128B rows),
// 3-stage cp.async ring, ONE barrier per stage. 96 KB/CTA -> 2 CTAs/SM.
// element (row, 16B-chunk ch) at byte  row*128 + ((ch ^ (row&7))<<4).
// A[M][K] half, Bt[N][K] half, fp32 accum.
// modes: 0 half out; 1 fp32 relu(v)+res; 2 half gelu(v); 3 fp32 v+res
// ---------------------------------------------------------------------------
#define TILE_B 16384                 // 128 rows x 128 bytes
#define STG_B  (2 * TILE_B)          // A + B tiles per stage
#define GEMM_SMEM_BYTES (3 * STG_B)  // 98304

__global__ __launch_bounds__(256, 2) void tgemm_kernel(
    const __half* __restrict__ A, const __half* __restrict__ Bt,
    const float* __restrict__ bias, const float* __restrict__ res,
    float* __restrict__ C, int M, int N, int K, int mode)
{
    extern __shared__ __half smh[];
    uint32_t smb = s2u(smh);

    int tid  = threadIdx.x;
    int lane = tid & 31;
    int wid  = tid >> 5;
    int wm   = wid >> 2;
    int wn   = wid & 3;
    int lr   = lane >> 2;
    int lc   = lane & 3;
    int mat  = lane >> 3;
    int l7   = lane & 7;

    int bn = blockIdx.x * 128;
    int bm = blockIdx.y * 128;

    // fragment lane addressing (swizzled)
    uint32_t aRow = (uint32_t)(wm * 64 + l7 + ((mat & 1) << 3)) * 128u;
    int aChSel = mat >> 1;                       // k-chunk lsb for A
    uint32_t bRow = (uint32_t)(wn * 32 + ((mat >> 1) << 3) + l7) * 128u;
    int bChSel = mat & 1;                        // k-chunk lsb for B

    // cp.async per-thread coords: idx = tid + t*256; row = idx>>3, ch = idx&7
    float acc[4][4][4];
    #pragma unroll
    for (int i = 0; i < 4; i++)
        #pragma unroll
        for (int j = 0; j < 4; j++)
            #pragma unroll
            for (int q = 0; q < 4; q++) acc[i][j][q] = 0.f;

    int NS = K >> 6;

    #pragma unroll
    for (int st = 0; st < 2; st++) {
        uint32_t Ab = smb + (uint32_t)st * STG_B;
        uint32_t Bb = Ab + TILE_B;
        int k0 = st * 64;
        #pragma unroll
        for (int t = 0; t < 4; t++) {
            int idx = tid + t * 256;
            int r = idx >> 3, ch = idx & 7;
            uint32_t off = (uint32_t)r * 128u + (uint32_t)((ch ^ (r & 7)) << 4);
            cpa16(Ab + off, A + (size_t)(bm + r) * K + k0 + ch * 8);
            cpa16(Bb + off, Bt + (size_t)(bn + r) * K + k0 + ch * 8);
        }
        asm volatile("cp.async.commit_group;" ::: "memory");
    }

    for (int s = 0; s < NS; s++) {
        if (s + 1 < NS) asm volatile("cp.async.wait_group 1;" ::: "memory");
        else            asm volatile("cp.async.wait_group 0;" ::: "memory");
        __syncthreads();

        // refill ring slot (s+2)%3 — its readers finished at stage s-1,
        // ordered by the barrier above.
        if (s + 2 < NS) {
            int b3 = (s + 2) % 3;
            uint32_t Ab2 = smb + (uint32_t)b3 * STG_B;
            uint32_t Bb2 = Ab2 + TILE_B;
            int k0 = (s + 2) * 64;
            #pragma unroll
            for (int t = 0; t < 4; t++) {
                int idx = tid + t * 256;
                int r = idx >> 3, ch = idx & 7;
                uint32_t off = (uint32_t)r * 128u + (uint32_t)((ch ^ (r & 7)) << 4);
                cpa16(Ab2 + off, A + (size_t)(bm + r) * K + k0 + ch * 8);
                cpa16(Bb2 + off, Bt + (size_t)(bn + r) * K + k0 + ch * 8);
            }
            asm volatile("cp.async.commit_group;" ::: "memory");
        }

        int cb = s % 3;
        uint32_t Ab = smb + (uint32_t)cb * STG_B;
        uint32_t Bb = Ab + TILE_B;

        #pragma unroll
        for (int kk = 0; kk < 4; kk++) {
            uint32_t aCh = (uint32_t)((((kk << 1) | aChSel) ^ l7) << 4);
            uint32_t bCh = (uint32_t)((((kk << 1) | bChSel) ^ l7) << 4);
            uint32_t af[4][4];
            #pragma unroll
            for (int mt = 0; mt < 4; mt++) {
                asm volatile(
                    "ldmatrix.sync.aligned.m8n8.x4.shared.b16 {%0,%1,%2,%3}, [%4];"
                    : "=r"(af[mt][0]), "=r"(af[mt][1]), "=r"(af[mt][2]), "=r"(af[mt][3])
                    : "r"(Ab + aRow + (uint32_t)(mt * 2048) + aCh));
            }
            uint32_t bf[4][2];
            #pragma unroll
            for (int p = 0; p < 2; p++) {
                asm volatile(
                    "ldmatrix.sync.aligned.m8n8.x4.shared.b16 {%0,%1,%2,%3}, [%4];"
                    : "=r"(bf[2*p][0]), "=r"(bf[2*p][1]),
                      "=r"(bf[2*p+1][0]), "=r"(bf[2*p+1][1])
                    : "r"(Bb + bRow + (uint32_t)(p * 2048) + bCh));
            }
            #pragma unroll
            for (int mt = 0; mt < 4; mt++)
                #pragma unroll
                for (int nt = 0; nt < 4; nt++) {
                    asm volatile(
                        "mma.sync.aligned.m16n8k16.row.col.f32.f16.f16.f32 "
                        "{%0,%1,%2,%3}, {%4,%5,%6,%7}, {%8,%9}, {%0,%1,%2,%3};"
                        : "+f"(acc[mt][nt][0]), "+f"(acc[mt][nt][1]),
                          "+f"(acc[mt][nt][2]), "+f"(acc[mt][nt][3])
                        : "r"(af[mt][0]), "r"(af[mt][1]), "r"(af[mt][2]), "r"(af[mt][3]),
                          "r"(bf[nt][0]), "r"(bf[nt][1]));
                }
        }
    }

    // ---- epilogue ----
    #pragma unroll
    for (int mt = 0; mt < 4; mt++) {
        #pragma unroll
        for (int half_ = 0; half_ < 2; half_++) {
            int row = bm + wm * 64 + mt * 16 + lr + half_ * 8;
            const float* rr = (mode == 1 || mode == 3) ? (res + (size_t)row * N) : nullptr;
            #pragma unroll
            for (int nt = 0; nt < 4; nt++) {
                int col = bn + wn * 32 + nt * 8 + lc * 2;
                float v0 = acc[mt][nt][half_ * 2 + 0] + bias[col];
                float v1 = acc[mt][nt][half_ * 2 + 1] + bias[col + 1];
                if (mode == 0) {
                    *(__half2*)((__half*)C + (size_t)row * N + col) = __floats2half2_rn(v0, v1);
                } else if (mode == 1) {
                    float2 o; o.x = fmaxf(v0, 0.f) + rr[col]; o.y = fmaxf(v1, 0.f) + rr[col + 1];
                    *(float2*)(C + (size_t)row * N + col) = o;
                } else if (mode == 2) {
                    v0 = 0.5f * v0 * (1.f + erff(v0 * 0.70710678118654752f));
                    v1 = 0.5f * v1 * (1.f + erff(v1 * 0.70710678118654752f));
                    *(__half2*)((__half*)C + (size_t)row * N + col) = __floats2half2_rn(v0, v1);
                } else {
                    float2 o; o.x = v0 + rr[col]; o.y = v1 + rr[col + 1];
                    *(float2*)(C + (size_t)row * N + col) = o;
                }
            }
        }
    }
}

// ---------------------------------------------------------------------------
// Flash attention, fp16 mma, cp.async double-buffered K/V.  (unchanged R10)
// ---------------------------------------------------------------------------
#define SP 72
#define KVT (64 * SP)
#define SQ_OFF 0
#define SK_OFF (128 * SP)
#define SV_OFF (SK_OFF + 2 * KVT)
#define ATTN_SMEM_BYTES ((SV_OFF + 2 * KVT) * 2)

__global__ __launch_bounds__(256, 2) void attn_kernel(
    const __half* __restrict__ QKV, __half* __restrict__ Og)
{
    extern __shared__ __half smh[];
    __half* sQ = smh + SQ_OFF;

    int bh = blockIdx.y;
    int b  = bh >> 4;
    int h  = bh & 15;
    int q0 = blockIdx.x * 128;

    size_t base = (size_t)b * 1024 * 3072;
    const __half* Qb = QKV + base + h * DKH;
    const __half* Kb = QKV + base + 1024 + h * DKH;
    const __half* Vb = QKV + base + 2048 + h * DKH;
    __half* Ob = Og + (size_t)b * 1024 * DMODEL + h * DKH;

    int tid  = threadIdx.x;
    int lane = tid & 31;
    int wid  = tid >> 5;
    int lr   = lane >> 2;
    int lc   = lane & 3;
    int mat  = lane >> 3;

    uint32_t sQb = s2u(sQ);
    uint32_t sKb0 = s2u(smh + SK_OFF);
    uint32_t sVb0 = s2u(smh + SV_OFF);
    uint32_t aoffQ = (uint32_t)(((wid * 16 + (lane & 7) + ((mat & 1) << 3)) * SP
                                + ((mat >> 1) << 3)) * 2);
    uint32_t koff  = (uint32_t)(((((mat >> 1) << 3) + (lane & 7)) * SP
                                + ((mat & 1) << 3)) * 2);
    uint32_t voff  = (uint32_t)(((((mat & 1) << 3) + (lane & 7)) * SP
                                + ((mat >> 1) << 3)) * 2);

    #pragma unroll
    for (int it = 0; it < 4; it++) {
        int idx = tid + it * 256;
        int r = idx >> 3, ch = idx & 7;
        *(uint4*)(sQ + r * SP + ch * 8) =
            *(const uint4*)(Qb + (size_t)(q0 + r) * 3072 + ch * 8);
    }

    #pragma unroll
    for (int it = 0; it < 2; it++) {
        int idx = tid + it * 256;
        int r = idx >> 3, ch = idx & 7;
        cpa16(sKb0 + (uint32_t)(r * SP + ch * 8) * 2,
              Kb + (size_t)r * 3072 + ch * 8);
        cpa16(sVb0 + (uint32_t)(r * SP + ch * 8) * 2,
              Vb + (size_t)r * 3072 + ch * 8);
    }
    asm volatile("cp.async.commit_group;" ::: "memory");

    float m0 = -1e30f, m1 = -1e30f, l0 = 0.f, l1 = 0.f;
    float o[8][4];
    #pragma unroll
    for (int nt = 0; nt < 8; nt++)
        #pragma unroll
        for (int q = 0; q < 4; q++) o[nt][q] = 0.f;

    for (int kt = 0; kt < 16; kt++) {
        asm volatile("cp.async.wait_group 0;" ::: "memory");
        __syncthreads();

        if (kt + 1 < 16) {
            int nb = (kt + 1) & 1;
            uint32_t Kd = sKb0 + (uint32_t)(nb * KVT) * 2;
            uint32_t Vd = sVb0 + (uint32_t)(nb * KVT) * 2;
            #pragma unroll
            for (int it = 0; it < 2; it++) {
                int idx = tid + it * 256;
                int r = idx >> 3, ch = idx & 7;
                cpa16(Kd + (uint32_t)(r * SP + ch * 8) * 2,
                      Kb + (size_t)((kt + 1) * 64 + r) * 3072 + ch * 8);
                cpa16(Vd + (uint32_t)(r * SP + ch * 8) * 2,
                      Vb + (size_t)((kt + 1) * 64 + r) * 3072 + ch * 8);
            }
            asm volatile("cp.async.commit_group;" ::: "memory");
        }

        uint32_t sKb = sKb0 + (uint32_t)((kt & 1) * KVT) * 2;
        uint32_t sVb = sVb0 + (uint32_t)((kt & 1) * KVT) * 2;

        float sc[8][4];
        #pragma unroll
        for (int nt = 0; nt < 8; nt++)
            #pragma unroll
            for (int q = 0; q < 4; q++) sc[nt][q] = 0.f;

        #pragma unroll
        for (int kk = 0; kk < 4; kk++) {
            uint32_t a0, a1, a2, a3;
            asm volatile(
                "ldmatrix.sync.aligned.m8n8.x4.shared.b16 {%0,%1,%2,%3}, [%4];"
                : "=r"(a0), "=r"(a1), "=r"(a2), "=r"(a3)
                : "r"(sQb + aoffQ + (uint32_t)(kk * 32)));
            uint32_t kf[8][2];
            #pragma unroll
            for (int p = 0; p < 4; p++) {
                asm volatile(
                    "ldmatrix.sync.aligned.m8n8.x4.shared.b16 {%0,%1,%2,%3}, [%4];"
                    : "=r"(kf[2*p][0]), "=r"(kf[2*p][1]),
                      "=r"(kf[2*p+1][0]), "=r"(kf[2*p+1][1])
                    : "r"(sKb + koff + (uint32_t)((p * 16 * SP + kk * 16) * 2)));
            }
            #pragma unroll
            for (int nt = 0; nt < 8; nt++) {
                asm volatile(
                    "mma.sync.aligned.m16n8k16.row.col.f32.f16.f16.f32 "
                    "{%0,%1,%2,%3}, {%4,%5,%6,%7}, {%8,%9}, {%0,%1,%2,%3};"
                    : "+f"(sc[nt][0]), "+f"(sc[nt][1]), "+f"(sc[nt][2]), "+f"(sc[nt][3])
                    : "r"(a0), "r"(a1), "r"(a2), "r"(a3),
                      "r"(kf[nt][0]), "r"(kf[nt][1]));
            }
        }

        float x0 = -1e30f, x1 = -1e30f;
        #pragma unroll
        for (int nt = 0; nt < 8; nt++) {
            x0 = fmaxf(x0, fmaxf(sc[nt][0], sc[nt][1]));
            x1 = fmaxf(x1, fmaxf(sc[nt][2], sc[nt][3]));
        }
        x0 = fmaxf(x0, __shfl_xor_sync(0xffffffffu, x0, 1));
        x0 = fmaxf(x0, __shfl_xor_sync(0xffffffffu, x0, 2));
        x1 = fmaxf(x1, __shfl_xor_sync(0xffffffffu, x1, 1));
        x1 = fmaxf(x1, __shfl_xor_sync(0xffffffffu, x1, 2));
        float mn0 = fmaxf(m0, x0), mn1 = fmaxf(m1, x1);
        float al0 = __expf(m0 - mn0), al1 = __expf(m1 - mn1);
        float su0 = 0.f, su1 = 0.f;
        #pragma unroll
        for (int nt = 0; nt < 8; nt++) {
            sc[nt][0] = __expf(sc[nt][0] - mn0);
            sc[nt][1] = __expf(sc[nt][1] - mn0);
            sc[nt][2] = __expf(sc[nt][2] - mn1);
            sc[nt][3] = __expf(sc[nt][3] - mn1);
            su0 += sc[nt][0] + sc[nt][1];
            su1 += sc[nt][2] + sc[nt][3];
            o[nt][0] *= al0; o[nt][1] *= al0;
            o[nt][2] *= al1; o[nt][3] *= al1;
        }
        su0 += __shfl_xor_sync(0xffffffffu, su0, 1);
        su0 += __shfl_xor_sync(0xffffffffu, su0, 2);
        su1 += __shfl_xor_sync(0xffffffffu, su1, 1);
        su1 += __shfl_xor_sync(0xffffffffu, su1, 2);
        l0 = l0 * al0 + su0;
        l1 = l1 * al1 + su1;
        m0 = mn0; m1 = mn1;

        #pragma unroll
        for (int kk = 0; kk < 4; kk++) {
            uint32_t pa0 = h2u(__floats2half2_rn(sc[2*kk][0],   sc[2*kk][1]));
            uint32_t pa1 = h2u(__floats2half2_rn(sc[2*kk][2],   sc[2*kk][3]));
            uint32_t pa2 = h2u(__floats2half2_rn(sc[2*kk+1][0], sc[2*kk+1][1]));
            uint32_t pa3 = h2u(__floats2half2_rn(sc[2*kk+1][2], sc[2*kk+1][3]));
            #pragma unroll
            for (int p = 0; p < 4; p++) {
                uint32_t vf[2][2];
                asm volatile(
                    "ldmatrix.sync.aligned.m8n8.x4.trans.shared.b16 {%0,%1,%2,%3}, [%4];"
                    : "=r"(vf[0][0]), "=r"(vf[0][1]), "=r"(vf[1][0]), "=r"(vf[1][1])
                    : "r"(sVb + voff + (uint32_t)((kk * 16 * SP + p * 16) * 2)));
                #pragma unroll
                for (int g = 0; g < 2; g++) {
                    int nt = p * 2 + g;
                    asm volatile(
                        "mma.sync.aligned.m16n8k16.row.col.f32.f16.f16.f32 "
                        "{%0,%1,%2,%3}, {%4,%5,%6,%7}, {%8,%9}, {%0,%1,%2,%3};"
                        : "+f"(o[nt][0]), "+f"(o[nt][1]), "+f"(o[nt][2]), "+f"(o[nt][3])
                        : "r"(pa0), "r"(pa1), "r"(pa2), "r"(pa3),
                          "r"(vf[g][0]), "r"(vf[g][1]));
                }
            }
        }
    }

    float inv0 = 1.f / l0, inv1 = 1.f / l1;
    int row0 = q0 + wid * 16 + lr;
    int row1 = row0 + 8;
    #pragma unroll
    for (int nt = 0; nt < 8; nt++) {
        int col = nt * 8 + lc * 2;
        *(__half2*)(Ob + (size_t)row0 * DMODEL + col) =
            __floats2half2_rn(o[nt][0] * inv0, o[nt][1] * inv0);
        *(__half2*)(Ob + (size_t)row1 * DMODEL + col) =
            __floats2half2_rn(o[nt][2] * inv1, o[nt][3] * inv1);
    }
}

// ---------------------------------------------------------------------------
// Host launcher
// ---------------------------------------------------------------------------
extern "C" void kernel_launch(void* const* d_in, const int* in_sizes, int n_in,
                              void* d_out, int out_size)
{
    const float* x     = (const float*)d_in[0];
    const float* ln1_w = (const float*)d_in[1];
    const float* ln1_b = (const float*)d_in[2];
    const float* wq    = (const float*)d_in[3];
    const float* bq    = (const float*)d_in[4];
    const float* wk    = (const float*)d_in[5];
    const float* bk    = (const float*)d_in[6];
    const float* wv    = (const float*)d_in[7];
    const float* bv    = (const float*)d_in[8];
    const float* wo    = (const float*)d_in[9];
    const float* bo    = (const float*)d_in[10];
    const float* ln2_w = (const float*)d_in[11];
    const float* ln2_b = (const float*)d_in[12];
    const float* w1    = (const float*)d_in[13];
    const float* b1    = (const float*)d_in[14];
    const float* w2    = (const float*)d_in[15];
    const float* b2    = (const float*)d_in[16];

    __half *p_h, *p_qkv, *p_ctx, *p_h2, *p_ff, *p_wh;
    float *p_out1, *p_bqkv;
    cudaGetSymbolAddress((void**)&p_h,    g_h);
    cudaGetSymbolAddress((void**)&p_qkv,  g_qkv);
    cudaGetSymbolAddress((void**)&p_ctx,  g_ctx);
    cudaGetSymbolAddress((void**)&p_out1, g_out1);
    cudaGetSymbolAddress((void**)&p_h2,   g_h2);
    cudaGetSymbolAddress((void**)&p_ff,   g_ff);
    cudaGetSymbolAddress((void**)&p_wh,   g_wh);
    cudaGetSymbolAddress((void**)&p_bqkv, g_bqkv);

    const int MB = 1024 * 1024;
    __half* wqkvT = p_wh;               // [3072][1024]
    __half* woT   = p_wh + 3 * MB;      // [1024][1024]
    __half* w1T   = p_wh + 4 * MB;      // [4096][1024]
    __half* w2T   = p_wh + 8 * MB;      // [1024][4096]

    cudaFuncSetAttribute(attn_kernel, cudaFuncAttributeMaxDynamicSharedMemorySize,
                         ATTN_SMEM_BYTES);
    cudaFuncSetAttribute(tgemm_kernel, cudaFuncAttributeMaxDynamicSharedMemorySize,
                         GEMM_SMEM_BYTES);

    // 0) weight prep
    transw4_kernel<<<dim3(32, 32, 4), 256>>>(wq, wk, wv, wo, bq, bk, bv, p_bqkv,
                                             wqkvT, woT);
    transw_kernel<<<dim3(128, 32), 256>>>(w1, w1T, 1024, 4096);
    transw_kernel<<<dim3(32, 128), 256>>>(w2, w2T, 4096, 1024);

    // 1) ln1 -> half
    ln_kernel<<<1024, 256>>>(x, ln1_w, ln1_b, p_h);
    // 2) fused QKV projection (half out)
    tgemm_kernel<<<dim3(24, 64), 256, GEMM_SMEM_BYTES>>>(
        p_h, wqkvT, p_bqkv, nullptr, (float*)p_qkv, TOK, 3 * DMODEL, DMODEL, 0);
    // 3) attention (fp16 mma, half out)
    attn_kernel<<<dim3(8, 128), 256, ATTN_SMEM_BYTES>>>(p_qkv, p_ctx);
    // 4) out proj + relu + residual(x) -> fp32 out1
    tgemm_kernel<<<dim3(8, 64), 256, GEMM_SMEM_BYTES>>>(
        p_ctx, woT, bo, x, p_out1, TOK, DMODEL, DMODEL, 1);
    // 5) ln2 -> half
    ln_kernel<<<1024, 256>>>(p_out1, ln2_w, ln2_b, p_h2);
    // 6) MLP up + gelu (half out)
    tgemm_kernel<<<dim3(32, 64), 256, GEMM_SMEM_BYTES>>>(
        p_h2, w1T, b1, nullptr, (float*)p_ff, TOK, DMLP, DMODEL, 2);
    // 7) MLP down + residual(out1) -> fp32 d_out
    tgemm_kernel<<<dim3(8, 64), 256, GEMM_SMEM_BYTES>>>(
        p_ff, w2T, b2, p_out1, (float*)d_out, TOK, DMODEL, DMLP, 3);
}

// round 15
// speedup vs baseline: 1.7350x; 1.0083x over previous
#include <cuda_runtime.h>
#include <cuda_fp16.h>
#include <math.h>
#include <stdint.h>

// ---------------------------------------------------------------------------
// Problem constants: B=8, S=1024, D=1024, H=16, DK=64, MLP=4096, tokens=8192
// ---------------------------------------------------------------------------
#define TOK    8192
#define DMODEL 1024
#define NHEAD  16
#define DKH    64
#define DMLP   4096
#define QSCALE (0.125f * 1.4426950408889634f)   // 1/sqrt(64) * log2(e)

// ---------------------------------------------------------------------------
// Scratch (device globals; no allocation allowed)
// ---------------------------------------------------------------------------
__device__ __half g_h   [TOK * DMODEL];
__device__ __half g_qkv [TOK * 3 * DMODEL];
__device__ __half g_ctx [TOK * DMODEL];
__device__ float  g_out1[TOK * DMODEL];
__device__ __half g_h2  [TOK * DMODEL];
__device__ __half g_ff  [TOK * DMLP];
__device__ __half g_wh  [12 * 1024 * 1024];  // wqkvT(3M) woT(1M) w1T(4M) w2T(4M)
__device__ float  g_bqkv[3072];

__device__ __forceinline__ uint32_t s2u(const void* p) {
    uint32_t a;
    asm("{ .reg .u64 t; cvta.to.shared.u64 t, %1; cvt.u32.u64 %0, t; }" : "=r"(a) : "l"(p));
    return a;
}
__device__ __forceinline__ void cpa16(uint32_t dst, const void* src) {
    asm volatile("cp.async.cg.shared.global [%0], [%1], 16;" :: "r"(dst), "l"(src) : "memory");
}
__device__ __forceinline__ uint32_t h2u(__half2 h) {
    union { __half2 h; uint32_t u; } c; c.h = h; return c.u;
}

// ---------------------------------------------------------------------------
// Weight prep: four 1024x1024 transposes in one launch (z selects matrix).
// z==0 blocks with blockIdx.y==0 additionally pack the QKV bias.
// Q weight/bias carry QSCALE (1/sqrt(dk) * log2 e) for exp2-softmax.
// ---------------------------------------------------------------------------
__global__ __launch_bounds__(256) void transw4_kernel(
    const float* __restrict__ wq, const float* __restrict__ wk,
    const float* __restrict__ wv, const float* __restrict__ wo,
    const float* __restrict__ bq, const float* __restrict__ bk,
    const float* __restrict__ bv, float* __restrict__ bqkv,
    __half* __restrict__ wqkvT, __half* __restrict__ woT)
{
    __shared__ float t[32][33];
    int z = blockIdx.z;
    const float* src = (z == 0) ? wq : (z == 1) ? wk : (z == 2) ? wv : wo;
    __half* dst = (z == 3) ? woT : (wqkvT + (size_t)z * 1024 * 1024);
    float scale = (z == 0) ? QSCALE : 1.f;
    int n0 = blockIdx.x * 32, k0 = blockIdx.y * 32;
    int tx = threadIdx.x & 31, ty = (threadIdx.x >> 5) * 4;
    #pragma unroll
    for (int i = 0; i < 4; i++)
        t[ty + i][tx] = src[(size_t)(k0 + ty + i) * 1024 + n0 + tx] * scale;
    __syncthreads();
    #pragma unroll
    for (int i = 0; i < 4; i++)
        dst[(size_t)(n0 + ty + i) * 1024 + k0 + tx] = __float2half_rn(t[tx][ty + i]);
    if (z == 0 && blockIdx.y == 0) {
        int i = blockIdx.x * 256 + threadIdx.x;
        if (i < 3072)
            bqkv[i] = (i < 1024) ? bq[i] * QSCALE
                    : (i < 2048) ? bk[i - 1024] : bv[i - 2048];
    }
}
// w1 + w2 transposes in ONE launch: bid<4096 -> w1 [1024x4096], else w2 [4096x1024]
__global__ __launch_bounds__(256) void transw2_kernel(
    const float* __restrict__ w1, __half* __restrict__ w1T,
    const float* __restrict__ w2, __half* __restrict__ w2T)
{
    __shared__ float t[32][33];
    int bid = blockIdx.x;
    const float* src; __half* dst; int Kd, Nd, n0, k0;
    if (bid < 4096) {
        src = w1; dst = w1T; Kd = 1024; Nd = 4096;
        n0 = (bid & 127) * 32; k0 = (bid >> 7) * 32;
    } else {
        bid -= 4096;
        src = w2; dst = w2T; Kd = 4096; Nd = 1024;
        n0 = (bid & 31) * 32; k0 = (bid >> 5) * 32;
    }
    int tx = threadIdx.x & 31, ty = (threadIdx.x >> 5) * 4;
    #pragma unroll
    for (int i = 0; i < 4; i++)
        t[ty + i][tx] = src[(size_t)(k0 + ty + i) * Nd + n0 + tx];
    __syncthreads();
    #pragma unroll
    for (int i = 0; i < 4; i++)
        dst[(size_t)(n0 + ty + i) * Kd + k0 + tx] = __float2half_rn(t[tx][ty + i]);
}

// ---------------------------------------------------------------------------
// LayerNorm: warp-per-row, two-pass (reduce, then reload from L1).
// Low register count -> high occupancy. grid 1024, block 256 (8 rows/block).
// ---------------------------------------------------------------------------
__global__ __launch_bounds__(256) void ln_kernel(
    const float* __restrict__ x, const float* __restrict__ w,
    const float* __restrict__ b, __half* __restrict__ out)
{
    int lane = threadIdx.x & 31;
    int row  = blockIdx.x * 8 + (threadIdx.x >> 5);
    const float4* xr = (const float4*)(x + (size_t)row * DMODEL);
    float s = 0.f, sq = 0.f;
    #pragma unroll
    for (int i = 0; i < 8; i++) {
        float4 v = xr[lane + i * 32];
        s  += v.x + v.y + v.z + v.w;
        sq += v.x*v.x + v.y*v.y + v.z*v.z + v.w*v.w;
    }
    #pragma unroll
    for (int o = 16; o; o >>= 1) {
        s  += __shfl_xor_sync(0xffffffffu, s,  o);
        sq += __shfl_xor_sync(0xffffffffu, sq, o);
    }
    float mu = s * (1.0f / DMODEL);
    float r  = rsqrtf(sq * (1.0f / DMODEL) - mu * mu + 1e-5f);
    __half2* orow = (__half2*)(out + (size_t)row * DMODEL);
    #pragma unroll
    for (int i = 0; i < 8; i++) {
        int idx = lane + i * 32;
        float4 v  = xr[idx];
        float4 w4 = ((const float4*)w)[idx];
        float4 b4 = ((const float4*)b)[idx];
        orow[idx * 2 + 0] = __floats2half2_rn((v.x - mu) * r * w4.x + b4.x,
                                              (v.y - mu) * r * w4.y + b4.y);
        orow[idx * 2 + 1] = __floats2half2_rn((v.z - mu) * r * w4.z + b4.z,
                                              (v.w - mu) * r * w4.w + b4.w);
    }
}

// ---------------------------------------------------------------------------
// fp16 mma.sync GEMM v5 (unchanged R11): XOR-swizzled smem, 3-stage ring,
// one barrier per stage. 96 KB/CTA -> 2 CTAs/SM.
// ---------------------------------------------------------------------------
#define TILE_B 16384
#define STG_B  (2 * TILE_B)
#define GEMM_SMEM_BYTES (3 * STG_B)

__global__ __launch_bounds__(256, 2) void tgemm_kernel(
    const __half* __restrict__ A, const __half* __restrict__ Bt,
    const float* __restrict__ bias, const float* __restrict__ res,
    float* __restrict__ C, int M, int N, int K, int mode)
{
    extern __shared__ __half smh[];
    uint32_t smb = s2u(smh);

    int tid  = threadIdx.x;
    int lane = tid & 31;
    int wid  = tid >> 5;
    int wm   = wid >> 2;
    int wn   = wid & 3;
    int lr   = lane >> 2;
    int lc   = lane & 3;
    int mat  = lane >> 3;
    int l7   = lane & 7;

    int bn = blockIdx.x * 128;
    int bm = blockIdx.y * 128;

    uint32_t aRow = (uint32_t)(wm * 64 + l7 + ((mat & 1) << 3)) * 128u;
    int aChSel = mat >> 1;
    uint32_t bRow = (uint32_t)(wn * 32 + ((mat >> 1) << 3) + l7) * 128u;
    int bChSel = mat & 1;

    float acc[4][4][4];
    #pragma unroll
    for (int i = 0; i < 4; i++)
        #pragma unroll
        for (int j = 0; j < 4; j++)
            #pragma unroll
            for (int q = 0; q < 4; q++) acc[i][j][q] = 0.f;

    int NS = K >> 6;

    #pragma unroll
    for (int st = 0; st < 2; st++) {
        uint32_t Ab = smb + (uint32_t)st * STG_B;
        uint32_t Bb = Ab + TILE_B;
        int k0 = st * 64;
        #pragma unroll
        for (int t = 0; t < 4; t++) {
            int idx = tid + t * 256;
            int r = idx >> 3, ch = idx & 7;
            uint32_t off = (uint32_t)r * 128u + (uint32_t)((ch ^ (r & 7)) << 4);
            cpa16(Ab + off, A + (size_t)(bm + r) * K + k0 + ch * 8);
            cpa16(Bb + off, Bt + (size_t)(bn + r) * K + k0 + ch * 8);
        }
        asm volatile("cp.async.commit_group;" ::: "memory");
    }

    for (int s = 0; s < NS; s++) {
        if (s + 1 < NS) asm volatile("cp.async.wait_group 1;" ::: "memory");
        else            asm volatile("cp.async.wait_group 0;" ::: "memory");
        __syncthreads();

        if (s + 2 < NS) {
            int b3 = (s + 2) % 3;
            uint32_t Ab2 = smb + (uint32_t)b3 * STG_B;
            uint32_t Bb2 = Ab2 + TILE_B;
            int k0 = (s + 2) * 64;
            #pragma unroll
            for (int t = 0; t < 4; t++) {
                int idx = tid + t * 256;
                int r = idx >> 3, ch = idx & 7;
                uint32_t off = (uint32_t)r * 128u + (uint32_t)((ch ^ (r & 7)) << 4);
                cpa16(Ab2 + off, A + (size_t)(bm + r) * K + k0 + ch * 8);
                cpa16(Bb2 + off, Bt + (size_t)(bn + r) * K + k0 + ch * 8);
            }
            asm volatile("cp.async.commit_group;" ::: "memory");
        }

        int cb = s % 3;
        uint32_t Ab = smb + (uint32_t)cb * STG_B;
        uint32_t Bb = Ab + TILE_B;

        #pragma unroll
        for (int kk = 0; kk < 4; kk++) {
            uint32_t aCh = (uint32_t)((((kk << 1) | aChSel) ^ l7) << 4);
            uint32_t bCh = (uint32_t)((((kk << 1) | bChSel) ^ l7) << 4);
            uint32_t af[4][4];
            #pragma unroll
            for (int mt = 0; mt < 4; mt++) {
                asm volatile(
                    "ldmatrix.sync.aligned.m8n8.x4.shared.b16 {%0,%1,%2,%3}, [%4];"
                    : "=r"(af[mt][0]), "=r"(af[mt][1]), "=r"(af[mt][2]), "=r"(af[mt][3])
                    : "r"(Ab + aRow + (uint32_t)(mt * 2048) + aCh));
            }
            uint32_t bf[4][2];
            #pragma unroll
            for (int p = 0; p < 2; p++) {
                asm volatile(
                    "ldmatrix.sync.aligned.m8n8.x4.shared.b16 {%0,%1,%2,%3}, [%4];"
                    : "=r"(bf[2*p][0]), "=r"(bf[2*p][1]),
                      "=r"(bf[2*p+1][0]), "=r"(bf[2*p+1][1])
                    : "r"(Bb + bRow + (uint32_t)(p * 2048) + bCh));
            }
            #pragma unroll
            for (int mt = 0; mt < 4; mt++)
                #pragma unroll
                for (int nt = 0; nt < 4; nt++) {
                    asm volatile(
                        "mma.sync.aligned.m16n8k16.row.col.f32.f16.f16.f32 "
                        "{%0,%1,%2,%3}, {%4,%5,%6,%7}, {%8,%9}, {%0,%1,%2,%3};"
                        : "+f"(acc[mt][nt][0]), "+f"(acc[mt][nt][1]),
                          "+f"(acc[mt][nt][2]), "+f"(acc[mt][nt][3])
                        : "r"(af[mt][0]), "r"(af[mt][1]), "r"(af[mt][2]), "r"(af[mt][3]),
                          "r"(bf[nt][0]), "r"(bf[nt][1]));
                }
        }
    }

    // ---- epilogue ----
    #pragma unroll
    for (int mt = 0; mt < 4; mt++) {
        #pragma unroll
        for (int half_ = 0; half_ < 2; half_++) {
            int row = bm + wm * 64 + mt * 16 + lr + half_ * 8;
            const float* rr = (mode == 1 || mode == 3) ? (res + (size_t)row * N) : nullptr;
            #pragma unroll
            for (int nt = 0; nt < 4; nt++) {
                int col = bn + wn * 32 + nt * 8 + lc * 2;
                float v0 = acc[mt][nt][half_ * 2 + 0] + bias[col];
                float v1 = acc[mt][nt][half_ * 2 + 1] + bias[col + 1];
                if (mode == 0) {
                    *(__half2*)((__half*)C + (size_t)row * N + col) = __floats2half2_rn(v0, v1);
                } else if (mode == 1) {
                    float2 o; o.x = fmaxf(v0, 0.f) + rr[col]; o.y = fmaxf(v1, 0.f) + rr[col + 1];
                    *(float2*)(C + (size_t)row * N + col) = o;
                } else if (mode == 2) {
                    v0 = 0.5f * v0 * (1.f + erff(v0 * 0.70710678118654752f));
                    v1 = 0.5f * v1 * (1.f + erff(v1 * 0.70710678118654752f));
                    *(__half2*)((__half*)C + (size_t)row * N + col) = __floats2half2_rn(v0, v1);
                } else {
                    float2 o; o.x = v0 + rr[col]; o.y = v1 + rr[col + 1];
                    *(float2*)(C + (size_t)row * N + col) = o;
                }
            }
        }
    }
}

// ---------------------------------------------------------------------------
// Flash attention, fp16 mma, cp.async double-buffered K/V, exp2 softmax
// (log2 e folded into Q projection). Otherwise unchanged from R11.
// ---------------------------------------------------------------------------
#define SP 72
#define KVT (64 * SP)
#define SQ_OFF 0
#define SK_OFF (128 * SP)
#define SV_OFF (SK_OFF + 2 * KVT)
#define ATTN_SMEM_BYTES ((SV_OFF + 2 * KVT) * 2)

__global__ __launch_bounds__(256, 2) void attn_kernel(
    const __half* __restrict__ QKV, __half* __restrict__ Og)
{
    extern __shared__ __half smh[];
    __half* sQ = smh + SQ_OFF;

    int bh = blockIdx.y;
    int b  = bh >> 4;
    int h  = bh & 15;
    int q0 = blockIdx.x * 128;

    size_t base = (size_t)b * 1024 * 3072;
    const __half* Qb = QKV + base + h * DKH;
    const __half* Kb = QKV + base + 1024 + h * DKH;
    const __half* Vb = QKV + base + 2048 + h * DKH;
    __half* Ob = Og + (size_t)b * 1024 * DMODEL + h * DKH;

    int tid  = threadIdx.x;
    int lane = tid & 31;
    int wid  = tid >> 5;
    int lr   = lane >> 2;
    int lc   = lane & 3;
    int mat  = lane >> 3;

    uint32_t sQb = s2u(sQ);
    uint32_t sKb0 = s2u(smh + SK_OFF);
    uint32_t sVb0 = s2u(smh + SV_OFF);
    uint32_t aoffQ = (uint32_t)(((wid * 16 + (lane & 7) + ((mat & 1) << 3)) * SP
                                + ((mat >> 1) << 3)) * 2);
    uint32_t koff  = (uint32_t)(((((mat >> 1) << 3) + (lane & 7)) * SP
                                + ((mat & 1) << 3)) * 2);
    uint32_t voff  = (uint32_t)(((((mat & 1) << 3) + (lane & 7)) * SP
                                + ((mat >> 1) << 3)) * 2);

    #pragma unroll
    for (int it = 0; it < 4; it++) {
        int idx = tid + it * 256;
        int r = idx >> 3, ch = idx & 7;
        *(uint4*)(sQ + r * SP + ch * 8) =
            *(const uint4*)(Qb + (size_t)(q0 + r) * 3072 + ch * 8);
    }

    #pragma unroll
    for (int it = 0; it < 2; it++) {
        int idx = tid + it * 256;
        int r = idx >> 3, ch = idx & 7;
        cpa16(sKb0 + (uint32_t)(r * SP + ch * 8) * 2,
              Kb + (size_t)r * 3072 + ch * 8);
        cpa16(sVb0 + (uint32_t)(r * SP + ch * 8) * 2,
              Vb + (size_t)r * 3072 + ch * 8);
    }
    asm volatile("cp.async.commit_group;" ::: "memory");

    float m0 = -1e30f, m1 = -1e30f, l0 = 0.f, l1 = 0.f;
    float o[8][4];
    #pragma unroll
    for (int nt = 0; nt < 8; nt++)
        #pragma unroll
        for (int q = 0; q < 4; q++) o[nt][q] = 0.f;

    for (int kt = 0; kt < 16; kt++) {
        asm volatile("cp.async.wait_group 0;" ::: "memory");
        __syncthreads();

        if (kt + 1 < 16) {
            int nb = (kt + 1) & 1;
            uint32_t Kd = sKb0 + (uint32_t)(nb * KVT) * 2;
            uint32_t Vd = sVb0 + (uint32_t)(nb * KVT) * 2;
            #pragma unroll
            for (int it = 0; it < 2; it++) {
                int idx = tid + it * 256;
                int r = idx >> 3, ch = idx & 7;
                cpa16(Kd + (uint32_t)(r * SP + ch * 8) * 2,
                      Kb + (size_t)((kt + 1) * 64 + r) * 3072 + ch * 8);
                cpa16(Vd + (uint32_t)(r * SP + ch * 8) * 2,
                      Vb + (size_t)((kt + 1) * 64 + r) * 3072 + ch * 8);
            }
            asm volatile("cp.async.commit_group;" ::: "memory");
        }

        uint32_t sKb = sKb0 + (uint32_t)((kt & 1) * KVT) * 2;
        uint32_t sVb = sVb0 + (uint32_t)((kt & 1) * KVT) * 2;

        float sc[8][4];
        #pragma unroll
        for (int nt = 0; nt < 8; nt++)
            #pragma unroll
            for (int q = 0; q < 4; q++) sc[nt][q] = 0.f;

        #pragma unroll
        for (int kk = 0; kk < 4; kk++) {
            uint32_t a0, a1, a2, a3;
            asm volatile(
                "ldmatrix.sync.aligned.m8n8.x4.shared.b16 {%0,%1,%2,%3}, [%4];"
                : "=r"(a0), "=r"(a1), "=r"(a2), "=r"(a3)
                : "r"(sQb + aoffQ + (uint32_t)(kk * 32)));
            uint32_t kf[8][2];
            #pragma unroll
            for (int p = 0; p < 4; p++) {
                asm volatile(
                    "ldmatrix.sync.aligned.m8n8.x4.shared.b16 {%0,%1,%2,%3}, [%4];"
                    : "=r"(kf[2*p][0]), "=r"(kf[2*p][1]),
                      "=r"(kf[2*p+1][0]), "=r"(kf[2*p+1][1])
                    : "r"(sKb + koff + (uint32_t)((p * 16 * SP + kk * 16) * 2)));
            }
            #pragma unroll
            for (int nt = 0; nt < 8; nt++) {
                asm volatile(
                    "mma.sync.aligned.m16n8k16.row.col.f32.f16.f16.f32 "
                    "{%0,%1,%2,%3}, {%4,%5,%6,%7}, {%8,%9}, {%0,%1,%2,%3};"
                    : "+f"(sc[nt][0]), "+f"(sc[nt][1]), "+f"(sc[nt][2]), "+f"(sc[nt][3])
                    : "r"(a0), "r"(a1), "r"(a2), "r"(a3),
                      "r"(kf[nt][0]), "r"(kf[nt][1]));
            }
        }

        // online softmax in log2-domain (scores pre-scaled by log2 e)
        float x0 = -1e30f, x1 = -1e30f;
        #pragma unroll
        for (int nt = 0; nt < 8; nt++) {
            x0 = fmaxf(x0, fmaxf(sc[nt][0], sc[nt][1]));
            x1 = fmaxf(x1, fmaxf(sc[nt][2], sc[nt][3]));
        }
        x0 = fmaxf(x0, __shfl_xor_sync(0xffffffffu, x0, 1));
        x0 = fmaxf(x0, __shfl_xor_sync(0xffffffffu, x0, 2));
        x1 = fmaxf(x1, __shfl_xor_sync(0xffffffffu, x1, 1));
        x1 = fmaxf(x1, __shfl_xor_sync(0xffffffffu, x1, 2));
        float mn0 = fmaxf(m0, x0), mn1 = fmaxf(m1, x1);
        float al0 = exp2f(m0 - mn0), al1 = exp2f(m1 - mn1);
        float su0 = 0.f, su1 = 0.f;
        #pragma unroll
        for (int nt = 0; nt < 8; nt++) {
            sc[nt][0] = exp2f(sc[nt][0] - mn0);
            sc[nt][1] = exp2f(sc[nt][1] - mn0);
            sc[nt][2] = exp2f(sc[nt][2] - mn1);
            sc[nt][3] = exp2f(sc[nt][3] - mn1);
            su0 += sc[nt][0] + sc[nt][1];
            su1 += sc[nt][2] + sc[nt][3];
            o[nt][0] *= al0; o[nt][1] *= al0;
            o[nt][2] *= al1; o[nt][3] *= al1;
        }
        su0 += __shfl_xor_sync(0xffffffffu, su0, 1);
        su0 += __shfl_xor_sync(0xffffffffu, su0, 2);
        su1 += __shfl_xor_sync(0xffffffffu, su1, 1);
        su1 += __shfl_xor_sync(0xffffffffu, su1, 2);
        l0 = l0 * al0 + su0;
        l1 = l1 * al1 + su1;
        m0 = mn0; m1 = mn1;

        #pragma unroll
        for (int kk = 0; kk < 4; kk++) {
            uint32_t pa0 = h2u(__floats2half2_rn(sc[2*kk][0],   sc[2*kk][1]));
            uint32_t pa1 = h2u(__floats2half2_rn(sc[2*kk][2],   sc[2*kk][3]));
            uint32_t pa2 = h2u(__floats2half2_rn(sc[2*kk+1][0], sc[2*kk+1][1]));
            uint32_t pa3 = h2u(__floats2half2_rn(sc[2*kk+1][2], sc[2*kk+1][3]));
            #pragma unroll
            for (int p = 0; p < 4; p++) {
                uint32_t vf[2][2];
                asm volatile(
                    "ldmatrix.sync.aligned.m8n8.x4.trans.shared.b16 {%0,%1,%2,%3}, [%4];"
                    : "=r"(vf[0][0]), "=r"(vf[0][1]), "=r"(vf[1][0]), "=r"(vf[1][1])
                    : "r"(sVb + voff + (uint32_t)((kk * 16 * SP + p * 16) * 2)));
                #pragma unroll
                for (int g = 0; g < 2; g++) {
                    int nt = p * 2 + g;
                    asm volatile(
                        "mma.sync.aligned.m16n8k16.row.col.f32.f16.f16.f32 "
                        "{%0,%1,%2,%3}, {%4,%5,%6,%7}, {%8,%9}, {%0,%1,%2,%3};"
                        : "+f"(o[nt][0]), "+f"(o[nt][1]), "+f"(o[nt][2]), "+f"(o[nt][3])
                        : "r"(pa0), "r"(pa1), "r"(pa2), "r"(pa3),
                          "r"(vf[g][0]), "r"(vf[g][1]));
                }
            }
        }
    }

    float inv0 = 1.f / l0, inv1 = 1.f / l1;
    int row0 = q0 + wid * 16 + lr;
    int row1 = row0 + 8;
    #pragma unroll
    for (int nt = 0; nt < 8; nt++) {
        int col = nt * 8 + lc * 2;
        *(__half2*)(Ob + (size_t)row0 * DMODEL + col) =
            __floats2half2_rn(o[nt][0] * inv0, o[nt][1] * inv0);
        *(__half2*)(Ob + (size_t)row1 * DMODEL + col) =
            __floats2half2_rn(o[nt][2] * inv1, o[nt][3] * inv1);
    }
}

// ---------------------------------------------------------------------------
// Host launcher
// ---------------------------------------------------------------------------
extern "C" void kernel_launch(void* const* d_in, const int* in_sizes, int n_in,
                              void* d_out, int out_size)
{
    const float* x     = (const float*)d_in[0];
    const float* ln1_w = (const float*)d_in[1];
    const float* ln1_b = (const float*)d_in[2];
    const float* wq    = (const float*)d_in[3];
    const float* bq    = (const float*)d_in[4];
    const float* wk    = (const float*)d_in[5];
    const float* bk    = (const float*)d_in[6];
    const float* wv    = (const float*)d_in[7];
    const float* bv    = (const float*)d_in[8];
    const float* wo    = (const float*)d_in[9];
    const float* bo    = (const float*)d_in[10];
    const float* ln2_w = (const float*)d_in[11];
    const float* ln2_b = (const float*)d_in[12];
    const float* w1    = (const float*)d_in[13];
    const float* b1    = (const float*)d_in[14];
    const float* w2    = (const float*)d_in[15];
    const float* b2    = (const float*)d_in[16];

    __half *p_h, *p_qkv, *p_ctx, *p_h2, *p_ff, *p_wh;
    float *p_out1, *p_bqkv;
    cudaGetSymbolAddress((void**)&p_h,    g_h);
    cudaGetSymbolAddress((void**)&p_qkv,  g_qkv);
    cudaGetSymbolAddress((void**)&p_ctx,  g_ctx);
    cudaGetSymbolAddress((void**)&p_out1, g_out1);
    cudaGetSymbolAddress((void**)&p_h2,   g_h2);
    cudaGetSymbolAddress((void**)&p_ff,   g_ff);
    cudaGetSymbolAddress((void**)&p_wh,   g_wh);
    cudaGetSymbolAddress((void**)&p_bqkv, g_bqkv);

    const int MB = 1024 * 1024;
    __half* wqkvT = p_wh;               // [3072][1024]
    __half* woT   = p_wh + 3 * MB;      // [1024][1024]
    __half* w1T   = p_wh + 4 * MB;      // [4096][1024]
    __half* w2T   = p_wh + 8 * MB;      // [1024][4096]

    cudaFuncSetAttribute(attn_kernel, cudaFuncAttributeMaxDynamicSharedMemorySize,
                         ATTN_SMEM_BYTES);
    cudaFuncSetAttribute(tgemm_kernel, cudaFuncAttributeMaxDynamicSharedMemorySize,
                         GEMM_SMEM_BYTES);

    // 0) weight prep
    transw4_kernel<<<dim3(32, 32, 4), 256>>>(wq, wk, wv, wo, bq, bk, bv, p_bqkv,
                                             wqkvT, woT);
    transw2_kernel<<<8192, 256>>>(w1, w1T, w2, w2T);

    // 1) ln1 -> half
    ln_kernel<<<1024, 256>>>(x, ln1_w, ln1_b, p_h);
    // 2) fused QKV projection (half out)
    tgemm_kernel<<<dim3(24, 64), 256, GEMM_SMEM_BYTES>>>(
        p_h, wqkvT, p_bqkv, nullptr, (float*)p_qkv, TOK, 3 * DMODEL, DMODEL, 0);
    // 3) attention (fp16 mma, exp2 softmax, half out)
    attn_kernel<<<dim3(8, 128), 256, ATTN_SMEM_BYTES>>>(p_qkv, p_ctx);
    // 4) out proj + relu + residual(x) -> fp32 out1
    tgemm_kernel<<<dim3(8, 64), 256, GEMM_SMEM_BYTES>>>(
        p_ctx, woT, bo, x, p_out1, TOK, DMODEL, DMODEL, 1);
    // 5) ln2 -> half
    ln_kernel<<<1024, 256>>>(p_out1, ln2_w, ln2_b, p_h2);
    // 6) MLP up + gelu (half out)
    tgemm_kernel<<<dim3(32, 64), 256, GEMM_SMEM_BYTES>>>(
        p_h2, w1T, b1, nullptr, (float*)p_ff, TOK, DMLP, DMODEL, 2);
    // 7) MLP down + residual(out1) -> fp32 d_out
    tgemm_kernel<<<dim3(8, 64), 256, GEMM_SMEM_BYTES>>>(
        p_ff, w2T, b2, p_out1, (float*)d_out, TOK, DMODEL, DMLP, 3);
}